// round 12
// baseline (speedup 1.0000x reference)
#include <cuda_runtime.h>
#include <cstdint>

#define DM 2048
#define DS 16
#define SEQ 4096
#define NB 4
#define NROWS (NB*SEQ)
#define CHL 32                 // chunk body length
#define CHW 20                 // warmup steps (contraction ~0.08^20 ~ 1e-22)
#define NCHUNK (SEQ/CHL)       // 128 chunks per batch

typedef unsigned long long u64;

// ---- scratch (static device arrays: no allocation allowed) ----
__device__ float  g_u[NROWS*DS + 1024]; // padded: prefetch overrun safe
__device__ float2 g_murs[NROWS];
__device__ float  g_hist2[NROWS*32];    // stride 32; lanes 16-31 write junk cols

__device__ __forceinline__ float tanh_fast(float x){
    float y;
    asm("tanh.approx.f32 %0, %1;" : "=f"(y) : "f"(x));
    return y;
}
// ---- packed f32x2 helpers (Blackwell FFMA2 path) ----
__device__ __forceinline__ u64 pk(float lo, float hi){
    u64 d; asm("mov.b64 %0, {%1, %2};" : "=l"(d) : "f"(lo), "f"(hi)); return d;
}
__device__ __forceinline__ float2 unpk(u64 a){
    float2 f; asm("mov.b64 {%0, %1}, %2;" : "=f"(f.x), "=f"(f.y) : "l"(a)); return f;
}
__device__ __forceinline__ u64 fma2(u64 a, u64 b, u64 c){
    u64 d; asm("fma.rn.f32x2 %0, %1, %2, %3;" : "=l"(d) : "l"(a), "l"(b), "l"(c)); return d;
}
__device__ __forceinline__ u64 mul2(u64 a, u64 b){
    u64 d; asm("mul.rn.f32x2 %0, %1, %2;" : "=l"(d) : "l"(a), "l"(b)); return d;
}
__device__ __forceinline__ u64 add2(u64 a, u64 b){
    u64 d; asm("add.rn.f32x2 %0, %1, %2;" : "=l"(d) : "l"(a), "l"(b)); return d;
}

// ---------------------------------------------------------------------------
// kernA: 256 threads, 8 d-elems/thread. Dots in packed f32x2 (xs pairs free
//   from float4 loads, bg packed at init): 128->64 FMA issues per row per
//   thread. Pipelined butterfly (R11) + single barrier + warp-0 tail.
// ---------------------------------------------------------------------------
__global__ __launch_bounds__(256, 1)
void kernA(const float* __restrict__ x,
           const float* __restrict__ B,
           const float* __restrict__ gamma,
           const float* __restrict__ beta){
    const int tid  = threadIdx.x;
    const int lane = tid & 31, warp = tid >> 5;
    const int d0   = tid * 8;
    const unsigned FULL = 0xFFFFFFFFu;

    __shared__ float spart[2][64][20];  // [buf][warp*8+lane(<8)][value(18)]
    __shared__ float scb[32];           // cB[16], bB[16]

    float gg[8], bt[8];
    {
        float4 t0 = *(const float4*)(gamma + d0);
        float4 t1 = *(const float4*)(gamma + d0 + 4);
        gg[0]=t0.x; gg[1]=t0.y; gg[2]=t0.z; gg[3]=t0.w;
        gg[4]=t1.x; gg[5]=t1.y; gg[6]=t1.z; gg[7]=t1.w;
        float4 u0 = *(const float4*)(beta + d0);
        float4 u1 = *(const float4*)(beta + d0 + 4);
        bt[0]=u0.x; bt[1]=u0.y; bt[2]=u0.z; bt[3]=u0.w;
        bt[4]=u1.x; bt[5]=u1.y; bt[6]=u1.z; bt[7]=u1.w;
    }

    u64 bg2[16][4];                    // gamma-folded B, packed pairs over k
    {
        float pc[16], pb[16];
        #pragma unroll
        for (int s = 0; s < 16; s++){
            float4 b0 = *(const float4*)(B + s*DM + d0);
            float4 b1 = *(const float4*)(B + s*DM + d0 + 4);
            float br[8] = {b0.x,b0.y,b0.z,b0.w,b1.x,b1.y,b1.z,b1.w};
            float bgs[8];
            float c = 0.f, b2 = 0.f;
            #pragma unroll
            for (int k = 0; k < 8; k++){
                bgs[k] = br[k] * gg[k];
                c  += bgs[k];
                b2  = fmaf(bt[k], br[k], b2);
            }
            bg2[s][0] = pk(bgs[0], bgs[1]);
            bg2[s][1] = pk(bgs[2], bgs[3]);
            bg2[s][2] = pk(bgs[4], bgs[5]);
            bg2[s][3] = pk(bgs[6], bgs[7]);
            pc[s] = c; pb[s] = b2;
        }
        #pragma unroll
        for (int off = 16; off > 0; off >>= 1){
            #pragma unroll
            for (int s = 0; s < 16; s++){
                pc[s] += __shfl_xor_sync(FULL, pc[s], off);
                pb[s] += __shfl_xor_sync(FULL, pb[s], off);
            }
        }
        if (lane == 0){
            #pragma unroll
            for (int s = 0; s < 16; s++){
                spart[0][warp][s]     = pc[s];
                spart[0][8 + warp][s] = pb[s];
            }
        }
        __syncthreads();
        if (tid < 32){
            int i = tid & 15, grp = tid >> 4;
            float t = spart[0][grp*8 + 0][i];
            #pragma unroll
            for (int w = 1; w < 8; w++) t += spart[0][grp*8 + w][i];
            scb[tid] = t;
        }
        __syncthreads();
    }
    float cBl = scb[lane & 15];
    float bBl = scb[16 + (lane & 15)];
    __syncthreads();

    const int stride = gridDim.x;
    int pbuf = 0;
    float pv[18];
    int   prow = -1;

    auto ldx4 = [&](int r, int off){
        int rc = r < NROWS ? r : 0;
        return *(const float4*)(x + (size_t)rc*DM + d0 + off);
    };
    int row = blockIdx.x;
    float4 xa = ldx4(row, 0),        xb = ldx4(row, 4);
    float4 xc = ldx4(row+stride, 0), xd = ldx4(row+stride, 4);

    for (; row < NROWS; row += stride){
        u64 x2[4] = { pk(xa.x, xa.y), pk(xa.z, xa.w),
                      pk(xb.x, xb.y), pk(xb.z, xb.w) };
        xa = xc; xb = xd;
        {
            int nr = row + 2*stride;
            xc = ldx4(nr, 0); xd = ldx4(nr, 4);
        }

        // ---- current row's dots (packed f32x2) ----
        float p[18];
        {
            u64 t = add2(add2(x2[0], x2[1]), add2(x2[2], x2[3]));
            u64 q = mul2(x2[0], x2[0]);
            q = fma2(x2[1], x2[1], q);
            q = fma2(x2[2], x2[2], q);
            q = fma2(x2[3], x2[3], q);
            float2 ft = unpk(t), fq = unpk(q);
            p[16] = ft.x + ft.y;
            p[17] = fq.x + fq.y;
        }
        #pragma unroll
        for (int s = 0; s < 16; s++){
            u64 acc = mul2(x2[0], bg2[s][0]);
            acc = fma2(x2[1], bg2[s][1], acc);
            acc = fma2(x2[2], bg2[s][2], acc);
            acc = fma2(x2[3], bg2[s][3], acc);
            float2 fa = unpk(acc);
            p[s] = fa.x + fa.y;
        }

        // ---- previous row's butterfly (pipelined) ----
        if (prow >= 0){
            #pragma unroll
            for (int i = 0; i < 18; i++) pv[i] += __shfl_xor_sync(FULL, pv[i], 16);
            #pragma unroll
            for (int i = 0; i < 18; i++) pv[i] += __shfl_xor_sync(FULL, pv[i], 8);
            if (lane < 8){
                float* dst = spart[pbuf][warp*8 + lane];
                *(float4*)(dst)      = make_float4(pv[0],  pv[1],  pv[2],  pv[3]);
                *(float4*)(dst + 4)  = make_float4(pv[4],  pv[5],  pv[6],  pv[7]);
                *(float4*)(dst + 8)  = make_float4(pv[8],  pv[9],  pv[10], pv[11]);
                *(float4*)(dst + 12) = make_float4(pv[12], pv[13], pv[14], pv[15]);
                *(float2*)(dst + 16) = make_float2(pv[16], pv[17]);
            }
            __syncthreads();
            if (warp == 0){
                float t0 = 0.f, t1 = 0.f, t2 = 0.f, t3 = 0.f;
                #pragma unroll
                for (int j = 0; j < 64; j += 4){
                    t0 += spart[pbuf][j    ][lane];
                    t1 += spart[pbuf][j + 1][lane];
                    t2 += spart[pbuf][j + 2][lane];
                    t3 += spart[pbuf][j + 3][lane];
                }
                float t = (t0 + t1) + (t2 + t3);
                float s1 = __shfl_sync(FULL, t, 16);
                float s2 = __shfl_sync(FULL, t, 17);
                float mu  = s1 * (1.0f/DM);
                float var = s2 * (1.0f/DM) - mu*mu;
                float rs  = rsqrtf(var + 1e-5f);
                if (lane < 16){
                    g_u[prow*DS + lane] = fmaf(-mu, cBl, t) * rs + bBl;
                } else if (lane == 16){
                    g_murs[prow] = make_float2(mu, rs);
                }
            }
            pbuf ^= 1;
        }

        #pragma unroll
        for (int i = 0; i < 18; i++) pv[i] = p[i];
        prow = row;
    }

    // ---- flush last row ----
    {
        #pragma unroll
        for (int i = 0; i < 18; i++) pv[i] += __shfl_xor_sync(FULL, pv[i], 16);
        #pragma unroll
        for (int i = 0; i < 18; i++) pv[i] += __shfl_xor_sync(FULL, pv[i], 8);
        if (lane < 8){
            float* dst = spart[pbuf][warp*8 + lane];
            *(float4*)(dst)      = make_float4(pv[0],  pv[1],  pv[2],  pv[3]);
            *(float4*)(dst + 4)  = make_float4(pv[4],  pv[5],  pv[6],  pv[7]);
            *(float4*)(dst + 8)  = make_float4(pv[8],  pv[9],  pv[10], pv[11]);
            *(float4*)(dst + 12) = make_float4(pv[12], pv[13], pv[14], pv[15]);
            *(float2*)(dst + 16) = make_float2(pv[16], pv[17]);
        }
        __syncthreads();
        if (warp == 0){
            float t0 = 0.f, t1 = 0.f, t2 = 0.f, t3 = 0.f;
            #pragma unroll
            for (int j = 0; j < 64; j += 4){
                t0 += spart[pbuf][j    ][lane];
                t1 += spart[pbuf][j + 1][lane];
                t2 += spart[pbuf][j + 2][lane];
                t3 += spart[pbuf][j + 3][lane];
            }
            float t = (t0 + t1) + (t2 + t3);
            float s1 = __shfl_sync(FULL, t, 16);
            float s2 = __shfl_sync(FULL, t, 17);
            float mu  = s1 * (1.0f/DM);
            float var = s2 * (1.0f/DM) - mu*mu;
            float rs  = rsqrtf(var + 1e-5f);
            if (lane < 16){
                g_u[prow*DS + lane] = fmaf(-mu, cBl, t) * rs + bBl;
            } else if (lane == 16){
                g_murs[prow] = make_float2(mu, rs);
            }
        }
    }
}

// ---------------------------------------------------------------------------
// kernScan: chunked-parallel exact scan (unchanged).
// ---------------------------------------------------------------------------
__global__ __launch_bounds__(32, 1)
void kernScan(const float* __restrict__ A){
    const int chunk = blockIdx.x;
    const int b     = chunk / NCHUNK;
    const int c     = chunk % NCHUNK;
    const int t0    = c * CHL;
    const int start = (c == 0) ? 0 : (t0 - CHW);
    const int steps = t0 + CHL - start;
    const int lane  = threadIdx.x;

    float a[16];
    #pragma unroll
    for (int j = 0; j < 16; j++) a[j] = A[j*DS + (lane & 15)];

    const float* ub = g_u     + (size_t)b * SEQ * DS + (size_t)start * DS;
    float*       hb = g_hist2 + (size_t)(b * SEQ + start) * 32;

    __shared__ float sh[2][32];
    sh[0][lane] = 0.f;
    __syncthreads();

    float uq[4];
    #pragma unroll
    for (int k = 0; k < 4; k++) uq[k] = ub[k*DS + lane];

    const int body0 = t0 - start;
    for (int s = 0; s < steps; s += 4){
        #pragma unroll
        for (int k = 0; k < 4; k++){
            const int i = s + k;
            const int p = i & 1;
            float uc = uq[k];
            uq[k] = ub[(i + 4)*DS + lane];

            float4 H0 = *(const float4*)&sh[p][0];
            float4 H1 = *(const float4*)&sh[p][4];
            float4 H2 = *(const float4*)&sh[p][8];
            float4 H3 = *(const float4*)&sh[p][12];

            float a0 = fmaf(H0.x, a[0], uc);
            float a1 = H0.y * a[1];
            float a2 = H0.z * a[2];
            float a3 = H0.w * a[3];
            float a4 = H1.x * a[4];
            float a5 = H1.y * a[5];
            float a6 = H1.z * a[6];
            float a7 = H1.w * a[7];
            a0 = fmaf(H2.x, a[8],  a0);
            a1 = fmaf(H2.y, a[9],  a1);
            a2 = fmaf(H2.z, a[10], a2);
            a3 = fmaf(H2.w, a[11], a3);
            a4 = fmaf(H3.x, a[12], a4);
            a5 = fmaf(H3.y, a[13], a5);
            a6 = fmaf(H3.z, a[14], a6);
            a7 = fmaf(H3.w, a[15], a7);
            float v = ((a0 + a1) + (a2 + a3)) + ((a4 + a5) + (a6 + a7));
            float h = tanh_fast(v);

            sh[p ^ 1][lane] = h;
            __syncthreads();

            if (i >= body0) hb[i*32 + lane] = h;
        }
    }
}

// ---------------------------------------------------------------------------
// kernC: out = h@C + (1+Dp)*(gamma*(x-mu)*rs + beta).  R8 shape + packed
//   f32x2 over the state dim (h pairs load packed from hist; cr packed at
//   init, same 64 regs). 128 -> 64 FMA issues per pair-iteration.
// ---------------------------------------------------------------------------
__global__ __launch_bounds__(256, 2)
void kernC(const float* __restrict__ x,
           const float* __restrict__ Cm,
           const float* __restrict__ Dp,
           const float* __restrict__ gamma,
           const float* __restrict__ beta,
           float* __restrict__ out){
    const int tid  = threadIdx.x;
    const int half = blockIdx.x & 1;
    const int d0   = half * (DM/2) + tid * 4;

    float e[4], f[4];
    {
        float4 dp = *(const float4*)(Dp    + d0);
        float4 g  = *(const float4*)(gamma + d0);
        float4 btv= *(const float4*)(beta  + d0);
        float dv[4] = {dp.x,dp.y,dp.z,dp.w};
        float gv[4] = {g.x,g.y,g.z,g.w};
        float bv[4] = {btv.x,btv.y,btv.z,btv.w};
        #pragma unroll
        for (int k = 0; k < 4; k++){
            float cc = 1.0f + dv[k];
            e[k] = cc * gv[k];
            f[k] = cc * bv[k];
        }
    }
    u64 cr2[8][4];                     // {C[2j][k], C[2j+1][k]} packed
    #pragma unroll
    for (int j = 0; j < 8; j++){
        float4 c0 = *(const float4*)(Cm + (2*j    )*DM + d0);
        float4 c1 = *(const float4*)(Cm + (2*j + 1)*DM + d0);
        cr2[j][0] = pk(c0.x, c1.x);
        cr2[j][1] = pk(c0.y, c1.y);
        cr2[j][2] = pk(c0.z, c1.z);
        cr2[j][3] = pk(c0.w, c1.w);
    }

    const int base = blockIdx.x >> 1;             // 0..147
    auto ldx = [&](int r){                        // clamp-indexed (branchless)
        int rc = r < NROWS ? r : NROWS-1;
        return *(const float4*)(x + (size_t)rc*DM + d0);
    };
    float4 x0 = ldx(base);
    float4 x1 = ldx(base + 148);
    float4 p0 = ldx(base + 296);
    float4 p1 = ldx(base + 444);

    for (int r = base; r < NROWS; r += 296){
        float4 c0 = x0, c1 = x1;
        x0 = p0; x1 = p1;
        p0 = ldx(r + 592);
        p1 = ldx(r + 740);

        int rB  = r + 148;
        int rBc = rB < NROWS ? rB : NROWS-1;

        float2 mrA = g_murs[r];
        float2 mrB = g_murs[rBc];
        const u64* hpA = (const u64*)(g_hist2 + (size_t)r*32);   // pairs packed free
        const u64* hpB = (const u64*)(g_hist2 + (size_t)rBc*32);
        u64 hA[8], hB[8];
        #pragma unroll
        for (int j = 0; j < 8; j++){ hA[j] = hpA[j]; hB[j] = hpB[j]; }

        float xsA[4] = {c0.x, c0.y, c0.z, c0.w};
        float xsB[4] = {c1.x, c1.y, c1.z, c1.w};
        float oA[4], oB[4];
        #pragma unroll
        for (int k = 0; k < 4; k++){
            float xcA = (xsA[k] - mrA.x) * mrA.y;
            float xcB = (xsB[k] - mrB.x) * mrB.y;
            u64 aA = mul2(hA[0], cr2[0][k]);
            u64 aB = mul2(hB[0], cr2[0][k]);
            #pragma unroll
            for (int j = 1; j < 8; j++){
                aA = fma2(hA[j], cr2[j][k], aA);
                aB = fma2(hB[j], cr2[j][k], aB);
            }
            float2 fA = unpk(aA), fB = unpk(aB);
            oA[k] = fmaf(e[k], xcA, f[k]) + fA.x + fA.y;
            oB[k] = fmaf(e[k], xcB, f[k]) + fB.x + fB.y;
        }
        *(float4*)(out + (size_t)r*DM + d0) = make_float4(oA[0], oA[1], oA[2], oA[3]);
        if (rB < NROWS)
            *(float4*)(out + (size_t)rB*DM + d0) = make_float4(oB[0], oB[1], oB[2], oB[3]);
    }
}

// ---------------------------------------------------------------------------
extern "C" void kernel_launch(void* const* d_in, const int* in_sizes, int n_in,
                              void* d_out, int out_size){
    const float* x     = (const float*)d_in[0];
    const float* A     = (const float*)d_in[1];
    const float* B     = (const float*)d_in[2];
    const float* C     = (const float*)d_in[3];
    const float* Dp    = (const float*)d_in[4];
    const float* gamma = (const float*)d_in[5];
    const float* beta  = (const float*)d_in[6];
    float* out = (float*)d_out;

    kernA<<<148, 256>>>(x, B, gamma, beta);
    kernScan<<<NB*NCHUNK, 32>>>(A);
    kernC<<<296, 256>>>(x, C, Dp, gamma, beta, out);
}

// round 13
// speedup vs baseline: 1.0948x; 1.0948x over previous
#include <cuda_runtime.h>
#include <cstdint>

#define DM 2048
#define DS 16
#define SEQ 4096
#define NB 4
#define NROWS (NB*SEQ)
#define CHL 32                 // chunk body length
#define CHW 20                 // warmup steps (contraction ~0.08^20 ~ 1e-22)
#define NCHUNK (SEQ/CHL)       // 128 chunks per batch

typedef unsigned long long u64;

// ---- scratch (static device arrays: no allocation allowed) ----
__device__ float  g_u[NROWS*DS + 1024]; // padded: prefetch overrun safe
__device__ float2 g_murs[NROWS];
__device__ float  g_hist2[NROWS*32];    // stride 32; lanes 16-31 write junk cols

__device__ __forceinline__ float tanh_fast(float x){
    float y;
    asm("tanh.approx.f32 %0, %1;" : "=f"(y) : "f"(x));
    return y;
}
// ---- packed f32x2 helpers (Blackwell FFMA2 path) ----
__device__ __forceinline__ u64 pk(float lo, float hi){
    u64 d; asm("mov.b64 %0, {%1, %2};" : "=l"(d) : "f"(lo), "f"(hi)); return d;
}
__device__ __forceinline__ float2 unpk(u64 a){
    float2 f; asm("mov.b64 {%0, %1}, %2;" : "=f"(f.x), "=f"(f.y) : "l"(a)); return f;
}
__device__ __forceinline__ u64 fma2(u64 a, u64 b, u64 c){
    u64 d; asm("fma.rn.f32x2 %0, %1, %2, %3;" : "=l"(d) : "l"(a), "l"(b), "l"(c)); return d;
}
__device__ __forceinline__ u64 mul2(u64 a, u64 b){
    u64 d; asm("mul.rn.f32x2 %0, %1, %2;" : "=l"(d) : "l"(a), "l"(b)); return d;
}
__device__ __forceinline__ u64 add2(u64 a, u64 b){
    u64 d; asm("add.rn.f32x2 %0, %1, %2;" : "=l"(d) : "l"(a), "l"(b)); return d;
}

// ---------------------------------------------------------------------------
// kernA: R12 shape (best measured: 74.9us). 256 threads, 8 d-elems/thread,
//   packed-f32x2 dots, pipelined butterfly, single barrier, warp-0 tail.
// ---------------------------------------------------------------------------
__global__ __launch_bounds__(256, 1)
void kernA(const float* __restrict__ x,
           const float* __restrict__ B,
           const float* __restrict__ gamma,
           const float* __restrict__ beta){
    const int tid  = threadIdx.x;
    const int lane = tid & 31, warp = tid >> 5;
    const int d0   = tid * 8;
    const unsigned FULL = 0xFFFFFFFFu;

    __shared__ float spart[2][64][20];  // [buf][warp*8+lane(<8)][value(18)]
    __shared__ float scb[32];           // cB[16], bB[16]

    float gg[8], bt[8];
    {
        float4 t0 = *(const float4*)(gamma + d0);
        float4 t1 = *(const float4*)(gamma + d0 + 4);
        gg[0]=t0.x; gg[1]=t0.y; gg[2]=t0.z; gg[3]=t0.w;
        gg[4]=t1.x; gg[5]=t1.y; gg[6]=t1.z; gg[7]=t1.w;
        float4 u0 = *(const float4*)(beta + d0);
        float4 u1 = *(const float4*)(beta + d0 + 4);
        bt[0]=u0.x; bt[1]=u0.y; bt[2]=u0.z; bt[3]=u0.w;
        bt[4]=u1.x; bt[5]=u1.y; bt[6]=u1.z; bt[7]=u1.w;
    }

    u64 bg2[16][4];                    // gamma-folded B, packed pairs over k
    {
        float pc[16], pb[16];
        #pragma unroll
        for (int s = 0; s < 16; s++){
            float4 b0 = *(const float4*)(B + s*DM + d0);
            float4 b1 = *(const float4*)(B + s*DM + d0 + 4);
            float br[8] = {b0.x,b0.y,b0.z,b0.w,b1.x,b1.y,b1.z,b1.w};
            float bgs[8];
            float c = 0.f, b2 = 0.f;
            #pragma unroll
            for (int k = 0; k < 8; k++){
                bgs[k] = br[k] * gg[k];
                c  += bgs[k];
                b2  = fmaf(bt[k], br[k], b2);
            }
            bg2[s][0] = pk(bgs[0], bgs[1]);
            bg2[s][1] = pk(bgs[2], bgs[3]);
            bg2[s][2] = pk(bgs[4], bgs[5]);
            bg2[s][3] = pk(bgs[6], bgs[7]);
            pc[s] = c; pb[s] = b2;
        }
        #pragma unroll
        for (int off = 16; off > 0; off >>= 1){
            #pragma unroll
            for (int s = 0; s < 16; s++){
                pc[s] += __shfl_xor_sync(FULL, pc[s], off);
                pb[s] += __shfl_xor_sync(FULL, pb[s], off);
            }
        }
        if (lane == 0){
            #pragma unroll
            for (int s = 0; s < 16; s++){
                spart[0][warp][s]     = pc[s];
                spart[0][8 + warp][s] = pb[s];
            }
        }
        __syncthreads();
        if (tid < 32){
            int i = tid & 15, grp = tid >> 4;
            float t = spart[0][grp*8 + 0][i];
            #pragma unroll
            for (int w = 1; w < 8; w++) t += spart[0][grp*8 + w][i];
            scb[tid] = t;
        }
        __syncthreads();
    }
    float cBl = scb[lane & 15];
    float bBl = scb[16 + (lane & 15)];
    __syncthreads();

    const int stride = gridDim.x;
    int pbuf = 0;
    float pv[18];
    int   prow = -1;

    auto ldx4 = [&](int r, int off){
        int rc = r < NROWS ? r : 0;
        return *(const float4*)(x + (size_t)rc*DM + d0 + off);
    };
    int row = blockIdx.x;
    float4 xa = ldx4(row, 0),        xb = ldx4(row, 4);
    float4 xc = ldx4(row+stride, 0), xd = ldx4(row+stride, 4);

    for (; row < NROWS; row += stride){
        u64 x2[4] = { pk(xa.x, xa.y), pk(xa.z, xa.w),
                      pk(xb.x, xb.y), pk(xb.z, xb.w) };
        xa = xc; xb = xd;
        {
            int nr = row + 2*stride;
            xc = ldx4(nr, 0); xd = ldx4(nr, 4);
        }

        // ---- current row's dots (packed f32x2) ----
        float p[18];
        {
            u64 t = add2(add2(x2[0], x2[1]), add2(x2[2], x2[3]));
            u64 q = mul2(x2[0], x2[0]);
            q = fma2(x2[1], x2[1], q);
            q = fma2(x2[2], x2[2], q);
            q = fma2(x2[3], x2[3], q);
            float2 ft = unpk(t), fq = unpk(q);
            p[16] = ft.x + ft.y;
            p[17] = fq.x + fq.y;
        }
        #pragma unroll
        for (int s = 0; s < 16; s++){
            u64 acc = mul2(x2[0], bg2[s][0]);
            acc = fma2(x2[1], bg2[s][1], acc);
            acc = fma2(x2[2], bg2[s][2], acc);
            acc = fma2(x2[3], bg2[s][3], acc);
            float2 fa = unpk(acc);
            p[s] = fa.x + fa.y;
        }

        // ---- previous row's butterfly (pipelined) ----
        if (prow >= 0){
            #pragma unroll
            for (int i = 0; i < 18; i++) pv[i] += __shfl_xor_sync(FULL, pv[i], 16);
            #pragma unroll
            for (int i = 0; i < 18; i++) pv[i] += __shfl_xor_sync(FULL, pv[i], 8);
            if (lane < 8){
                float* dst = spart[pbuf][warp*8 + lane];
                *(float4*)(dst)      = make_float4(pv[0],  pv[1],  pv[2],  pv[3]);
                *(float4*)(dst + 4)  = make_float4(pv[4],  pv[5],  pv[6],  pv[7]);
                *(float4*)(dst + 8)  = make_float4(pv[8],  pv[9],  pv[10], pv[11]);
                *(float4*)(dst + 12) = make_float4(pv[12], pv[13], pv[14], pv[15]);
                *(float2*)(dst + 16) = make_float2(pv[16], pv[17]);
            }
            __syncthreads();
            if (warp == 0){
                float t0 = 0.f, t1 = 0.f, t2 = 0.f, t3 = 0.f;
                #pragma unroll
                for (int j = 0; j < 64; j += 4){
                    t0 += spart[pbuf][j    ][lane];
                    t1 += spart[pbuf][j + 1][lane];
                    t2 += spart[pbuf][j + 2][lane];
                    t3 += spart[pbuf][j + 3][lane];
                }
                float t = (t0 + t1) + (t2 + t3);
                float s1 = __shfl_sync(FULL, t, 16);
                float s2 = __shfl_sync(FULL, t, 17);
                float mu  = s1 * (1.0f/DM);
                float var = s2 * (1.0f/DM) - mu*mu;
                float rs  = rsqrtf(var + 1e-5f);
                if (lane < 16){
                    g_u[prow*DS + lane] = fmaf(-mu, cBl, t) * rs + bBl;
                } else if (lane == 16){
                    g_murs[prow] = make_float2(mu, rs);
                }
            }
            pbuf ^= 1;
        }

        #pragma unroll
        for (int i = 0; i < 18; i++) pv[i] = p[i];
        prow = row;
    }

    // ---- flush last row ----
    {
        #pragma unroll
        for (int i = 0; i < 18; i++) pv[i] += __shfl_xor_sync(FULL, pv[i], 16);
        #pragma unroll
        for (int i = 0; i < 18; i++) pv[i] += __shfl_xor_sync(FULL, pv[i], 8);
        if (lane < 8){
            float* dst = spart[pbuf][warp*8 + lane];
            *(float4*)(dst)      = make_float4(pv[0],  pv[1],  pv[2],  pv[3]);
            *(float4*)(dst + 4)  = make_float4(pv[4],  pv[5],  pv[6],  pv[7]);
            *(float4*)(dst + 8)  = make_float4(pv[8],  pv[9],  pv[10], pv[11]);
            *(float4*)(dst + 12) = make_float4(pv[12], pv[13], pv[14], pv[15]);
            *(float2*)(dst + 16) = make_float2(pv[16], pv[17]);
        }
        __syncthreads();
        if (warp == 0){
            float t0 = 0.f, t1 = 0.f, t2 = 0.f, t3 = 0.f;
            #pragma unroll
            for (int j = 0; j < 64; j += 4){
                t0 += spart[pbuf][j    ][lane];
                t1 += spart[pbuf][j + 1][lane];
                t2 += spart[pbuf][j + 2][lane];
                t3 += spart[pbuf][j + 3][lane];
            }
            float t = (t0 + t1) + (t2 + t3);
            float s1 = __shfl_sync(FULL, t, 16);
            float s2 = __shfl_sync(FULL, t, 17);
            float mu  = s1 * (1.0f/DM);
            float var = s2 * (1.0f/DM) - mu*mu;
            float rs  = rsqrtf(var + 1e-5f);
            if (lane < 16){
                g_u[prow*DS + lane] = fmaf(-mu, cBl, t) * rs + bBl;
            } else if (lane == 16){
                g_murs[prow] = make_float2(mu, rs);
            }
        }
    }
}

// ---------------------------------------------------------------------------
// kernScan: chunked-parallel exact scan (unchanged).
// ---------------------------------------------------------------------------
__global__ __launch_bounds__(32, 1)
void kernScan(const float* __restrict__ A){
    const int chunk = blockIdx.x;
    const int b     = chunk / NCHUNK;
    const int c     = chunk % NCHUNK;
    const int t0    = c * CHL;
    const int start = (c == 0) ? 0 : (t0 - CHW);
    const int steps = t0 + CHL - start;
    const int lane  = threadIdx.x;

    float a[16];
    #pragma unroll
    for (int j = 0; j < 16; j++) a[j] = A[j*DS + (lane & 15)];

    const float* ub = g_u     + (size_t)b * SEQ * DS + (size_t)start * DS;
    float*       hb = g_hist2 + (size_t)(b * SEQ + start) * 32;

    __shared__ float sh[2][32];
    sh[0][lane] = 0.f;
    __syncthreads();

    float uq[4];
    #pragma unroll
    for (int k = 0; k < 4; k++) uq[k] = ub[k*DS + lane];

    const int body0 = t0 - start;
    for (int s = 0; s < steps; s += 4){
        #pragma unroll
        for (int k = 0; k < 4; k++){
            const int i = s + k;
            const int p = i & 1;
            float uc = uq[k];
            uq[k] = ub[(i + 4)*DS + lane];

            float4 H0 = *(const float4*)&sh[p][0];
            float4 H1 = *(const float4*)&sh[p][4];
            float4 H2 = *(const float4*)&sh[p][8];
            float4 H3 = *(const float4*)&sh[p][12];

            float a0 = fmaf(H0.x, a[0], uc);
            float a1 = H0.y * a[1];
            float a2 = H0.z * a[2];
            float a3 = H0.w * a[3];
            float a4 = H1.x * a[4];
            float a5 = H1.y * a[5];
            float a6 = H1.z * a[6];
            float a7 = H1.w * a[7];
            a0 = fmaf(H2.x, a[8],  a0);
            a1 = fmaf(H2.y, a[9],  a1);
            a2 = fmaf(H2.z, a[10], a2);
            a3 = fmaf(H2.w, a[11], a3);
            a4 = fmaf(H3.x, a[12], a4);
            a5 = fmaf(H3.y, a[13], a5);
            a6 = fmaf(H3.z, a[14], a6);
            a7 = fmaf(H3.w, a[15], a7);
            float v = ((a0 + a1) + (a2 + a3)) + ((a4 + a5) + (a6 + a7));
            float h = tanh_fast(v);

            sh[p ^ 1][lane] = h;
            __syncthreads();

            if (i >= body0) hb[i*32 + lane] = h;
        }
    }
}

// ---------------------------------------------------------------------------
// kernC: exact R8 scalar shape (measured 73us) + prefetch deepened to
//   3 row-pairs (6 outstanding LDG.128/thread for DRAM MLP).
// ---------------------------------------------------------------------------
__global__ __launch_bounds__(256, 2)
void kernC(const float* __restrict__ x,
           const float* __restrict__ Cm,
           const float* __restrict__ Dp,
           const float* __restrict__ gamma,
           const float* __restrict__ beta,
           float* __restrict__ out){
    const int tid  = threadIdx.x;
    const int half = blockIdx.x & 1;
    const int d0   = half * (DM/2) + tid * 4;

    float e[4], f[4];
    {
        float4 dp = *(const float4*)(Dp    + d0);
        float4 g  = *(const float4*)(gamma + d0);
        float4 btv= *(const float4*)(beta  + d0);
        float dv[4] = {dp.x,dp.y,dp.z,dp.w};
        float gv[4] = {g.x,g.y,g.z,g.w};
        float bv[4] = {btv.x,btv.y,btv.z,btv.w};
        #pragma unroll
        for (int k = 0; k < 4; k++){
            float cc = 1.0f + dv[k];
            e[k] = cc * gv[k];
            f[k] = cc * bv[k];
        }
    }
    float cr[16][4];
    #pragma unroll
    for (int s = 0; s < 16; s++){
        float4 c0 = *(const float4*)(Cm + s*DM + d0);
        cr[s][0]=c0.x; cr[s][1]=c0.y; cr[s][2]=c0.z; cr[s][3]=c0.w;
    }

    const int base = blockIdx.x >> 1;             // 0..147
    auto ldx = [&](int r){                        // clamp-indexed (branchless)
        int rc = r < NROWS ? r : NROWS-1;
        return *(const float4*)(x + (size_t)rc*DM + d0);
    };
    float4 x0 = ldx(base);
    float4 x1 = ldx(base + 148);
    float4 p0 = ldx(base + 296);
    float4 p1 = ldx(base + 444);
    float4 q0 = ldx(base + 592);
    float4 q1 = ldx(base + 740);

    for (int r = base; r < NROWS; r += 296){
        float4 c0 = x0, c1 = x1;
        x0 = p0; x1 = p1;
        p0 = q0; p1 = q1;
        q0 = ldx(r + 888);
        q1 = ldx(r + 1036);

        int rB  = r + 148;
        int rBc = rB < NROWS ? rB : NROWS-1;

        float2 mrA = g_murs[r];
        float2 mrB = g_murs[rBc];
        const float4* hpA = (const float4*)(g_hist2 + (size_t)r*32);
        const float4* hpB = (const float4*)(g_hist2 + (size_t)rBc*32);
        float4 hA0 = hpA[0], hA1 = hpA[1], hA2 = hpA[2], hA3 = hpA[3];
        float4 hB0 = hpB[0], hB1 = hpB[1], hB2 = hpB[2], hB3 = hpB[3];
        float hvA[16] = {hA0.x,hA0.y,hA0.z,hA0.w, hA1.x,hA1.y,hA1.z,hA1.w,
                         hA2.x,hA2.y,hA2.z,hA2.w, hA3.x,hA3.y,hA3.z,hA3.w};
        float hvB[16] = {hB0.x,hB0.y,hB0.z,hB0.w, hB1.x,hB1.y,hB1.z,hB1.w,
                         hB2.x,hB2.y,hB2.z,hB2.w, hB3.x,hB3.y,hB3.z,hB3.w};

        float xsA[4] = {c0.x, c0.y, c0.z, c0.w};
        float xsB[4] = {c1.x, c1.y, c1.z, c1.w};
        float oA[4], oB[4];
        #pragma unroll
        for (int k = 0; k < 4; k++){
            float xcA = (xsA[k] - mrA.x) * mrA.y;
            float xcB = (xsB[k] - mrB.x) * mrB.y;
            float aA  = fmaf(e[k], xcA, f[k]);
            float aB  = fmaf(e[k], xcB, f[k]);
            #pragma unroll
            for (int s = 0; s < 16; s++){
                aA = fmaf(hvA[s], cr[s][k], aA);
                aB = fmaf(hvB[s], cr[s][k], aB);
            }
            oA[k] = aA; oB[k] = aB;
        }
        *(float4*)(out + (size_t)r*DM + d0) = make_float4(oA[0], oA[1], oA[2], oA[3]);
        if (rB < NROWS)
            *(float4*)(out + (size_t)rB*DM + d0) = make_float4(oB[0], oB[1], oB[2], oB[3]);
    }
}

// ---------------------------------------------------------------------------
extern "C" void kernel_launch(void* const* d_in, const int* in_sizes, int n_in,
                              void* d_out, int out_size){
    const float* x     = (const float*)d_in[0];
    const float* A     = (const float*)d_in[1];
    const float* B     = (const float*)d_in[2];
    const float* C     = (const float*)d_in[3];
    const float* Dp    = (const float*)d_in[4];
    const float* gamma = (const float*)d_in[5];
    const float* beta  = (const float*)d_in[6];
    float* out = (float*)d_out;

    kernA<<<148, 256>>>(x, B, gamma, beta);
    kernScan<<<NB*NCHUNK, 32>>>(A);
    kernC<<<296, 256>>>(x, C, Dp, gamma, beta, out);
}

// round 14
// speedup vs baseline: 1.2766x; 1.1660x over previous
#include <cuda_runtime.h>
#include <cstdint>

#define DM 2048
#define DS 16
#define SEQ 4096
#define NB 4
#define NROWS (NB*SEQ)
#define CHL 32                 // chunk body length
#define CHW 20                 // warmup steps (contraction ~0.08^20 ~ 1e-22)
#define NCHUNK (SEQ/CHL)       // 128 chunks per batch

typedef unsigned long long u64;

// ---- scratch (static device arrays: no allocation allowed) ----
__device__ float  g_u[NROWS*DS + 1024]; // padded: prefetch overrun safe
__device__ float2 g_murs[NROWS];
__device__ float  g_hist2[NROWS*32];    // stride 32; lanes 16-31 write junk cols

__device__ __forceinline__ float tanh_fast(float x){
    float y;
    asm("tanh.approx.f32 %0, %1;" : "=f"(y) : "f"(x));
    return y;
}
// ---- packed f32x2 helpers (Blackwell FFMA2 path) ----
__device__ __forceinline__ u64 pk(float lo, float hi){
    u64 d; asm("mov.b64 %0, {%1, %2};" : "=l"(d) : "f"(lo), "f"(hi)); return d;
}
__device__ __forceinline__ float2 unpk(u64 a){
    float2 f; asm("mov.b64 {%0, %1}, %2;" : "=f"(f.x), "=f"(f.y) : "l"(a)); return f;
}
__device__ __forceinline__ u64 fma2(u64 a, u64 b, u64 c){
    u64 d; asm("fma.rn.f32x2 %0, %1, %2, %3;" : "=l"(d) : "l"(a), "l"(b), "l"(c)); return d;
}
__device__ __forceinline__ u64 mul2(u64 a, u64 b){
    u64 d; asm("mul.rn.f32x2 %0, %1, %2;" : "=l"(d) : "l"(a), "l"(b)); return d;
}
__device__ __forceinline__ u64 add2(u64 a, u64 b){
    u64 d; asm("add.rn.f32x2 %0, %1, %2;" : "=l"(d) : "l"(a), "l"(b)); return d;
}

// ---------------------------------------------------------------------------
// kernA: 256 threads, 8 d-elems/thread, packed-f32x2 dots, pipelined
//   butterfly. R14 change: THREE butterfly rounds (16/8/4) -> 32 partials,
//   halving the serial warp-0 tail (the barrier critical path).
// ---------------------------------------------------------------------------
__global__ __launch_bounds__(256, 1)
void kernA(const float* __restrict__ x,
           const float* __restrict__ B,
           const float* __restrict__ gamma,
           const float* __restrict__ beta){
    const int tid  = threadIdx.x;
    const int lane = tid & 31, warp = tid >> 5;
    const int d0   = tid * 8;
    const unsigned FULL = 0xFFFFFFFFu;

    __shared__ float spart[2][32][20];  // [buf][warp*4+lane(<4)][value(18)]
    __shared__ float scb[32];           // cB[16], bB[16]

    float gg[8], bt[8];
    {
        float4 t0 = *(const float4*)(gamma + d0);
        float4 t1 = *(const float4*)(gamma + d0 + 4);
        gg[0]=t0.x; gg[1]=t0.y; gg[2]=t0.z; gg[3]=t0.w;
        gg[4]=t1.x; gg[5]=t1.y; gg[6]=t1.z; gg[7]=t1.w;
        float4 u0 = *(const float4*)(beta + d0);
        float4 u1 = *(const float4*)(beta + d0 + 4);
        bt[0]=u0.x; bt[1]=u0.y; bt[2]=u0.z; bt[3]=u0.w;
        bt[4]=u1.x; bt[5]=u1.y; bt[6]=u1.z; bt[7]=u1.w;
    }

    u64 bg2[16][4];                    // gamma-folded B, packed pairs over k
    {
        float pc[16], pb[16];
        #pragma unroll
        for (int s = 0; s < 16; s++){
            float4 b0 = *(const float4*)(B + s*DM + d0);
            float4 b1 = *(const float4*)(B + s*DM + d0 + 4);
            float br[8] = {b0.x,b0.y,b0.z,b0.w,b1.x,b1.y,b1.z,b1.w};
            float bgs[8];
            float c = 0.f, b2 = 0.f;
            #pragma unroll
            for (int k = 0; k < 8; k++){
                bgs[k] = br[k] * gg[k];
                c  += bgs[k];
                b2  = fmaf(bt[k], br[k], b2);
            }
            bg2[s][0] = pk(bgs[0], bgs[1]);
            bg2[s][1] = pk(bgs[2], bgs[3]);
            bg2[s][2] = pk(bgs[4], bgs[5]);
            bg2[s][3] = pk(bgs[6], bgs[7]);
            pc[s] = c; pb[s] = b2;
        }
        #pragma unroll
        for (int off = 16; off > 0; off >>= 1){
            #pragma unroll
            for (int s = 0; s < 16; s++){
                pc[s] += __shfl_xor_sync(FULL, pc[s], off);
                pb[s] += __shfl_xor_sync(FULL, pb[s], off);
            }
        }
        if (lane == 0){
            #pragma unroll
            for (int s = 0; s < 16; s++){
                spart[0][warp][s]     = pc[s];
                spart[0][8 + warp][s] = pb[s];
            }
        }
        __syncthreads();
        if (tid < 32){
            int i = tid & 15, grp = tid >> 4;
            float t = spart[0][grp*8 + 0][i];
            #pragma unroll
            for (int w = 1; w < 8; w++) t += spart[0][grp*8 + w][i];
            scb[tid] = t;
        }
        __syncthreads();
    }
    float cBl = scb[lane & 15];
    float bBl = scb[16 + (lane & 15)];
    __syncthreads();

    const int stride = gridDim.x;
    int pbuf = 0;
    float pv[18];
    int   prow = -1;

    auto ldx4 = [&](int r, int off){
        int rc = r < NROWS ? r : 0;
        return *(const float4*)(x + (size_t)rc*DM + d0 + off);
    };
    int row = blockIdx.x;
    float4 xa = ldx4(row, 0),        xb = ldx4(row, 4);
    float4 xc = ldx4(row+stride, 0), xd = ldx4(row+stride, 4);

    for (; row < NROWS; row += stride){
        u64 x2[4] = { pk(xa.x, xa.y), pk(xa.z, xa.w),
                      pk(xb.x, xb.y), pk(xb.z, xb.w) };
        xa = xc; xb = xd;
        {
            int nr = row + 2*stride;
            xc = ldx4(nr, 0); xd = ldx4(nr, 4);
        }

        // ---- current row's dots (packed f32x2) ----
        float p[18];
        {
            u64 t = add2(add2(x2[0], x2[1]), add2(x2[2], x2[3]));
            u64 q = mul2(x2[0], x2[0]);
            q = fma2(x2[1], x2[1], q);
            q = fma2(x2[2], x2[2], q);
            q = fma2(x2[3], x2[3], q);
            float2 ft = unpk(t), fq = unpk(q);
            p[16] = ft.x + ft.y;
            p[17] = fq.x + fq.y;
        }
        #pragma unroll
        for (int s = 0; s < 16; s++){
            u64 acc = mul2(x2[0], bg2[s][0]);
            acc = fma2(x2[1], bg2[s][1], acc);
            acc = fma2(x2[2], bg2[s][2], acc);
            acc = fma2(x2[3], bg2[s][3], acc);
            float2 fa = unpk(acc);
            p[s] = fa.x + fa.y;
        }

        // ---- previous row's butterfly (pipelined, 3 rounds -> lanes 0-3) ----
        if (prow >= 0){
            #pragma unroll
            for (int i = 0; i < 18; i++) pv[i] += __shfl_xor_sync(FULL, pv[i], 16);
            #pragma unroll
            for (int i = 0; i < 18; i++) pv[i] += __shfl_xor_sync(FULL, pv[i], 8);
            #pragma unroll
            for (int i = 0; i < 18; i++) pv[i] += __shfl_xor_sync(FULL, pv[i], 4);
            if (lane < 4){
                float* dst = spart[pbuf][warp*4 + lane];
                *(float4*)(dst)      = make_float4(pv[0],  pv[1],  pv[2],  pv[3]);
                *(float4*)(dst + 4)  = make_float4(pv[4],  pv[5],  pv[6],  pv[7]);
                *(float4*)(dst + 8)  = make_float4(pv[8],  pv[9],  pv[10], pv[11]);
                *(float4*)(dst + 12) = make_float4(pv[12], pv[13], pv[14], pv[15]);
                *(float2*)(dst + 16) = make_float2(pv[16], pv[17]);
            }
            __syncthreads();
            if (warp == 0){            // serial tail halved: 32 partials
                float t0 = 0.f, t1 = 0.f, t2 = 0.f, t3 = 0.f;
                #pragma unroll
                for (int j = 0; j < 32; j += 4){
                    t0 += spart[pbuf][j    ][lane];
                    t1 += spart[pbuf][j + 1][lane];
                    t2 += spart[pbuf][j + 2][lane];
                    t3 += spart[pbuf][j + 3][lane];
                }
                float t = (t0 + t1) + (t2 + t3);
                float s1 = __shfl_sync(FULL, t, 16);
                float s2 = __shfl_sync(FULL, t, 17);
                float mu  = s1 * (1.0f/DM);
                float var = s2 * (1.0f/DM) - mu*mu;
                float rs  = rsqrtf(var + 1e-5f);
                if (lane < 16){
                    g_u[prow*DS + lane] = fmaf(-mu, cBl, t) * rs + bBl;
                } else if (lane == 16){
                    g_murs[prow] = make_float2(mu, rs);
                }
            }
            pbuf ^= 1;
        }

        #pragma unroll
        for (int i = 0; i < 18; i++) pv[i] = p[i];
        prow = row;
    }

    // ---- flush last row ----
    {
        #pragma unroll
        for (int i = 0; i < 18; i++) pv[i] += __shfl_xor_sync(FULL, pv[i], 16);
        #pragma unroll
        for (int i = 0; i < 18; i++) pv[i] += __shfl_xor_sync(FULL, pv[i], 8);
        #pragma unroll
        for (int i = 0; i < 18; i++) pv[i] += __shfl_xor_sync(FULL, pv[i], 4);
        if (lane < 4){
            float* dst = spart[pbuf][warp*4 + lane];
            *(float4*)(dst)      = make_float4(pv[0],  pv[1],  pv[2],  pv[3]);
            *(float4*)(dst + 4)  = make_float4(pv[4],  pv[5],  pv[6],  pv[7]);
            *(float4*)(dst + 8)  = make_float4(pv[8],  pv[9],  pv[10], pv[11]);
            *(float4*)(dst + 12) = make_float4(pv[12], pv[13], pv[14], pv[15]);
            *(float2*)(dst + 16) = make_float2(pv[16], pv[17]);
        }
        __syncthreads();
        if (warp == 0){
            float t0 = 0.f, t1 = 0.f, t2 = 0.f, t3 = 0.f;
            #pragma unroll
            for (int j = 0; j < 32; j += 4){
                t0 += spart[pbuf][j    ][lane];
                t1 += spart[pbuf][j + 1][lane];
                t2 += spart[pbuf][j + 2][lane];
                t3 += spart[pbuf][j + 3][lane];
            }
            float t = (t0 + t1) + (t2 + t3);
            float s1 = __shfl_sync(FULL, t, 16);
            float s2 = __shfl_sync(FULL, t, 17);
            float mu  = s1 * (1.0f/DM);
            float var = s2 * (1.0f/DM) - mu*mu;
            float rs  = rsqrtf(var + 1e-5f);
            if (lane < 16){
                g_u[prow*DS + lane] = fmaf(-mu, cBl, t) * rs + bBl;
            } else if (lane == 16){
                g_murs[prow] = make_float2(mu, rs);
            }
        }
    }
}

// ---------------------------------------------------------------------------
// kernScan: chunked-parallel exact scan (unchanged).
// ---------------------------------------------------------------------------
__global__ __launch_bounds__(32, 1)
void kernScan(const float* __restrict__ A){
    const int chunk = blockIdx.x;
    const int b     = chunk / NCHUNK;
    const int c     = chunk % NCHUNK;
    const int t0    = c * CHL;
    const int start = (c == 0) ? 0 : (t0 - CHW);
    const int steps = t0 + CHL - start;
    const int lane  = threadIdx.x;

    float a[16];
    #pragma unroll
    for (int j = 0; j < 16; j++) a[j] = A[j*DS + (lane & 15)];

    const float* ub = g_u     + (size_t)b * SEQ * DS + (size_t)start * DS;
    float*       hb = g_hist2 + (size_t)(b * SEQ + start) * 32;

    __shared__ float sh[2][32];
    sh[0][lane] = 0.f;
    __syncthreads();

    float uq[4];
    #pragma unroll
    for (int k = 0; k < 4; k++) uq[k] = ub[k*DS + lane];

    const int body0 = t0 - start;
    for (int s = 0; s < steps; s += 4){
        #pragma unroll
        for (int k = 0; k < 4; k++){
            const int i = s + k;
            const int p = i & 1;
            float uc = uq[k];
            uq[k] = ub[(i + 4)*DS + lane];

            float4 H0 = *(const float4*)&sh[p][0];
            float4 H1 = *(const float4*)&sh[p][4];
            float4 H2 = *(const float4*)&sh[p][8];
            float4 H3 = *(const float4*)&sh[p][12];

            float a0 = fmaf(H0.x, a[0], uc);
            float a1 = H0.y * a[1];
            float a2 = H0.z * a[2];
            float a3 = H0.w * a[3];
            float a4 = H1.x * a[4];
            float a5 = H1.y * a[5];
            float a6 = H1.z * a[6];
            float a7 = H1.w * a[7];
            a0 = fmaf(H2.x, a[8],  a0);
            a1 = fmaf(H2.y, a[9],  a1);
            a2 = fmaf(H2.z, a[10], a2);
            a3 = fmaf(H2.w, a[11], a3);
            a4 = fmaf(H3.x, a[12], a4);
            a5 = fmaf(H3.y, a[13], a5);
            a6 = fmaf(H3.z, a[14], a6);
            a7 = fmaf(H3.w, a[15], a7);
            float v = ((a0 + a1) + (a2 + a3)) + ((a4 + a5) + (a6 + a7));
            float h = tanh_fast(v);

            sh[p ^ 1][lane] = h;
            __syncthreads();

            if (i >= body0) hb[i*32 + lane] = h;
        }
    }
}

// ---------------------------------------------------------------------------
// kernC: R8 scalar shape + streaming cache hints: x read with __ldcs (last
//   use), out written with __stcs (write-once) to keep L2 for C/hist/murs.
// ---------------------------------------------------------------------------
__global__ __launch_bounds__(256, 2)
void kernC(const float* __restrict__ x,
           const float* __restrict__ Cm,
           const float* __restrict__ Dp,
           const float* __restrict__ gamma,
           const float* __restrict__ beta,
           float* __restrict__ out){
    const int tid  = threadIdx.x;
    const int half = blockIdx.x & 1;
    const int d0   = half * (DM/2) + tid * 4;

    float e[4], f[4];
    {
        float4 dp = *(const float4*)(Dp    + d0);
        float4 g  = *(const float4*)(gamma + d0);
        float4 btv= *(const float4*)(beta  + d0);
        float dv[4] = {dp.x,dp.y,dp.z,dp.w};
        float gv[4] = {g.x,g.y,g.z,g.w};
        float bv[4] = {btv.x,btv.y,btv.z,btv.w};
        #pragma unroll
        for (int k = 0; k < 4; k++){
            float cc = 1.0f + dv[k];
            e[k] = cc * gv[k];
            f[k] = cc * bv[k];
        }
    }
    float cr[16][4];
    #pragma unroll
    for (int s = 0; s < 16; s++){
        float4 c0 = *(const float4*)(Cm + s*DM + d0);
        cr[s][0]=c0.x; cr[s][1]=c0.y; cr[s][2]=c0.z; cr[s][3]=c0.w;
    }

    const int base = blockIdx.x >> 1;             // 0..147
    auto ldx = [&](int r){                        // clamp-indexed (branchless)
        int rc = r < NROWS ? r : NROWS-1;
        return __ldcs((const float4*)(x + (size_t)rc*DM + d0));
    };
    float4 x0 = ldx(base);
    float4 x1 = ldx(base + 148);
    float4 p0 = ldx(base + 296);
    float4 p1 = ldx(base + 444);

    for (int r = base; r < NROWS; r += 296){
        float4 c0 = x0, c1 = x1;
        x0 = p0; x1 = p1;
        p0 = ldx(r + 592);
        p1 = ldx(r + 740);

        int rB  = r + 148;
        int rBc = rB < NROWS ? rB : NROWS-1;

        float2 mrA = g_murs[r];
        float2 mrB = g_murs[rBc];
        const float4* hpA = (const float4*)(g_hist2 + (size_t)r*32);
        const float4* hpB = (const float4*)(g_hist2 + (size_t)rBc*32);
        float4 hA0 = hpA[0], hA1 = hpA[1], hA2 = hpA[2], hA3 = hpA[3];
        float4 hB0 = hpB[0], hB1 = hpB[1], hB2 = hpB[2], hB3 = hpB[3];
        float hvA[16] = {hA0.x,hA0.y,hA0.z,hA0.w, hA1.x,hA1.y,hA1.z,hA1.w,
                         hA2.x,hA2.y,hA2.z,hA2.w, hA3.x,hA3.y,hA3.z,hA3.w};
        float hvB[16] = {hB0.x,hB0.y,hB0.z,hB0.w, hB1.x,hB1.y,hB1.z,hB1.w,
                         hB2.x,hB2.y,hB2.z,hB2.w, hB3.x,hB3.y,hB3.z,hB3.w};

        float xsA[4] = {c0.x, c0.y, c0.z, c0.w};
        float xsB[4] = {c1.x, c1.y, c1.z, c1.w};
        float oA[4], oB[4];
        #pragma unroll
        for (int k = 0; k < 4; k++){
            float xcA = (xsA[k] - mrA.x) * mrA.y;
            float xcB = (xsB[k] - mrB.x) * mrB.y;
            float aA  = fmaf(e[k], xcA, f[k]);
            float aB  = fmaf(e[k], xcB, f[k]);
            #pragma unroll
            for (int s = 0; s < 16; s++){
                aA = fmaf(hvA[s], cr[s][k], aA);
                aB = fmaf(hvB[s], cr[s][k], aB);
            }
            oA[k] = aA; oB[k] = aB;
        }
        __stcs((float4*)(out + (size_t)r*DM + d0),
               make_float4(oA[0], oA[1], oA[2], oA[3]));
        if (rB < NROWS)
            __stcs((float4*)(out + (size_t)rB*DM + d0),
                   make_float4(oB[0], oB[1], oB[2], oB[3]));
    }
}

// ---------------------------------------------------------------------------
extern "C" void kernel_launch(void* const* d_in, const int* in_sizes, int n_in,
                              void* d_out, int out_size){
    const float* x     = (const float*)d_in[0];
    const float* A     = (const float*)d_in[1];
    const float* B     = (const float*)d_in[2];
    const float* C     = (const float*)d_in[3];
    const float* Dp    = (const float*)d_in[4];
    const float* gamma = (const float*)d_in[5];
    const float* beta  = (const float*)d_in[6];
    float* out = (float*)d_out;

    kernA<<<148, 256>>>(x, B, gamma, beta);
    kernScan<<<NB*NCHUNK, 32>>>(A);
    kernC<<<296, 256>>>(x, C, Dp, gamma, beta, out);
}

// round 15
// speedup vs baseline: 1.2909x; 1.0113x over previous
#include <cuda_runtime.h>
#include <cstdint>

#define DM 2048
#define DS 16
#define SEQ 4096
#define NB 4
#define NROWS (NB*SEQ)
#define CHL 32                 // chunk body length
#define CHW 20                 // warmup steps (contraction ~0.08^20 ~ 1e-22)
#define NCHUNK (SEQ/CHL)       // 128 chunks per batch

typedef unsigned long long u64;

// ---- scratch (static device arrays: no allocation allowed) ----
__device__ float  g_u[NROWS*DS + 1024]; // padded: prefetch overrun safe
__device__ float2 g_murs[NROWS];
__device__ float  g_hist2[NROWS*32];    // stride 32; lanes 16-31 write junk cols

__device__ __forceinline__ float tanh_fast(float x){
    float y;
    asm("tanh.approx.f32 %0, %1;" : "=f"(y) : "f"(x));
    return y;
}
// ---- packed f32x2 helpers (Blackwell FFMA2 path) ----
__device__ __forceinline__ u64 pk(float lo, float hi){
    u64 d; asm("mov.b64 %0, {%1, %2};" : "=l"(d) : "f"(lo), "f"(hi)); return d;
}
__device__ __forceinline__ float2 unpk(u64 a){
    float2 f; asm("mov.b64 {%0, %1}, %2;" : "=f"(f.x), "=f"(f.y) : "l"(a)); return f;
}
__device__ __forceinline__ u64 fma2(u64 a, u64 b, u64 c){
    u64 d; asm("fma.rn.f32x2 %0, %1, %2, %3;" : "=l"(d) : "l"(a), "l"(b), "l"(c)); return d;
}
__device__ __forceinline__ u64 mul2(u64 a, u64 b){
    u64 d; asm("mul.rn.f32x2 %0, %1, %2;" : "=l"(d) : "l"(a), "l"(b)); return d;
}
__device__ __forceinline__ u64 add2(u64 a, u64 b){
    u64 d; asm("add.rn.f32x2 %0, %1, %2;" : "=l"(d) : "l"(a), "l"(b)); return d;
}

// ---------------------------------------------------------------------------
// kernA: R12 shape (best measured: 74.9us) + __ldcs streaming x loads.
//   256 threads, 8 d-elems/thread, packed-f32x2 dots, pipelined 2-round
//   butterfly, single barrier per row, warp-0 tail overlapped.
// ---------------------------------------------------------------------------
__global__ __launch_bounds__(256, 1)
void kernA(const float* __restrict__ x,
           const float* __restrict__ B,
           const float* __restrict__ gamma,
           const float* __restrict__ beta){
    const int tid  = threadIdx.x;
    const int lane = tid & 31, warp = tid >> 5;
    const int d0   = tid * 8;
    const unsigned FULL = 0xFFFFFFFFu;

    __shared__ float spart[2][64][20];  // [buf][warp*8+lane(<8)][value(18)]
    __shared__ float scb[32];           // cB[16], bB[16]

    float gg[8], bt[8];
    {
        float4 t0 = *(const float4*)(gamma + d0);
        float4 t1 = *(const float4*)(gamma + d0 + 4);
        gg[0]=t0.x; gg[1]=t0.y; gg[2]=t0.z; gg[3]=t0.w;
        gg[4]=t1.x; gg[5]=t1.y; gg[6]=t1.z; gg[7]=t1.w;
        float4 u0 = *(const float4*)(beta + d0);
        float4 u1 = *(const float4*)(beta + d0 + 4);
        bt[0]=u0.x; bt[1]=u0.y; bt[2]=u0.z; bt[3]=u0.w;
        bt[4]=u1.x; bt[5]=u1.y; bt[6]=u1.z; bt[7]=u1.w;
    }

    u64 bg2[16][4];                    // gamma-folded B, packed pairs over k
    {
        float pc[16], pb[16];
        #pragma unroll
        for (int s = 0; s < 16; s++){
            float4 b0 = *(const float4*)(B + s*DM + d0);
            float4 b1 = *(const float4*)(B + s*DM + d0 + 4);
            float br[8] = {b0.x,b0.y,b0.z,b0.w,b1.x,b1.y,b1.z,b1.w};
            float bgs[8];
            float c = 0.f, b2 = 0.f;
            #pragma unroll
            for (int k = 0; k < 8; k++){
                bgs[k] = br[k] * gg[k];
                c  += bgs[k];
                b2  = fmaf(bt[k], br[k], b2);
            }
            bg2[s][0] = pk(bgs[0], bgs[1]);
            bg2[s][1] = pk(bgs[2], bgs[3]);
            bg2[s][2] = pk(bgs[4], bgs[5]);
            bg2[s][3] = pk(bgs[6], bgs[7]);
            pc[s] = c; pb[s] = b2;
        }
        #pragma unroll
        for (int off = 16; off > 0; off >>= 1){
            #pragma unroll
            for (int s = 0; s < 16; s++){
                pc[s] += __shfl_xor_sync(FULL, pc[s], off);
                pb[s] += __shfl_xor_sync(FULL, pb[s], off);
            }
        }
        if (lane == 0){
            #pragma unroll
            for (int s = 0; s < 16; s++){
                spart[0][warp][s]     = pc[s];
                spart[0][8 + warp][s] = pb[s];
            }
        }
        __syncthreads();
        if (tid < 32){
            int i = tid & 15, grp = tid >> 4;
            float t = spart[0][grp*8 + 0][i];
            #pragma unroll
            for (int w = 1; w < 8; w++) t += spart[0][grp*8 + w][i];
            scb[tid] = t;
        }
        __syncthreads();
    }
    float cBl = scb[lane & 15];
    float bBl = scb[16 + (lane & 15)];
    __syncthreads();

    const int stride = gridDim.x;
    int pbuf = 0;
    float pv[18];
    int   prow = -1;

    auto ldx4 = [&](int r, int off){
        int rc = r < NROWS ? r : 0;
        return __ldcs((const float4*)(x + (size_t)rc*DM + d0 + off));
    };
    int row = blockIdx.x;
    float4 xa = ldx4(row, 0),        xb = ldx4(row, 4);
    float4 xc = ldx4(row+stride, 0), xd = ldx4(row+stride, 4);

    for (; row < NROWS; row += stride){
        u64 x2[4] = { pk(xa.x, xa.y), pk(xa.z, xa.w),
                      pk(xb.x, xb.y), pk(xb.z, xb.w) };
        xa = xc; xb = xd;
        {
            int nr = row + 2*stride;
            xc = ldx4(nr, 0); xd = ldx4(nr, 4);
        }

        // ---- current row's dots (packed f32x2) ----
        float p[18];
        {
            u64 t = add2(add2(x2[0], x2[1]), add2(x2[2], x2[3]));
            u64 q = mul2(x2[0], x2[0]);
            q = fma2(x2[1], x2[1], q);
            q = fma2(x2[2], x2[2], q);
            q = fma2(x2[3], x2[3], q);
            float2 ft = unpk(t), fq = unpk(q);
            p[16] = ft.x + ft.y;
            p[17] = fq.x + fq.y;
        }
        #pragma unroll
        for (int s = 0; s < 16; s++){
            u64 acc = mul2(x2[0], bg2[s][0]);
            acc = fma2(x2[1], bg2[s][1], acc);
            acc = fma2(x2[2], bg2[s][2], acc);
            acc = fma2(x2[3], bg2[s][3], acc);
            float2 fa = unpk(acc);
            p[s] = fa.x + fa.y;
        }

        // ---- previous row's butterfly (pipelined, 2 rounds -> lanes 0-7) ----
        if (prow >= 0){
            #pragma unroll
            for (int i = 0; i < 18; i++) pv[i] += __shfl_xor_sync(FULL, pv[i], 16);
            #pragma unroll
            for (int i = 0; i < 18; i++) pv[i] += __shfl_xor_sync(FULL, pv[i], 8);
            if (lane < 8){
                float* dst = spart[pbuf][warp*8 + lane];
                *(float4*)(dst)      = make_float4(pv[0],  pv[1],  pv[2],  pv[3]);
                *(float4*)(dst + 4)  = make_float4(pv[4],  pv[5],  pv[6],  pv[7]);
                *(float4*)(dst + 8)  = make_float4(pv[8],  pv[9],  pv[10], pv[11]);
                *(float4*)(dst + 12) = make_float4(pv[12], pv[13], pv[14], pv[15]);
                *(float2*)(dst + 16) = make_float2(pv[16], pv[17]);
            }
            __syncthreads();
            if (warp == 0){
                float t0 = 0.f, t1 = 0.f, t2 = 0.f, t3 = 0.f;
                #pragma unroll
                for (int j = 0; j < 64; j += 4){
                    t0 += spart[pbuf][j    ][lane];
                    t1 += spart[pbuf][j + 1][lane];
                    t2 += spart[pbuf][j + 2][lane];
                    t3 += spart[pbuf][j + 3][lane];
                }
                float t = (t0 + t1) + (t2 + t3);
                float s1 = __shfl_sync(FULL, t, 16);
                float s2 = __shfl_sync(FULL, t, 17);
                float mu  = s1 * (1.0f/DM);
                float var = s2 * (1.0f/DM) - mu*mu;
                float rs  = rsqrtf(var + 1e-5f);
                if (lane < 16){
                    g_u[prow*DS + lane] = fmaf(-mu, cBl, t) * rs + bBl;
                } else if (lane == 16){
                    g_murs[prow] = make_float2(mu, rs);
                }
            }
            pbuf ^= 1;
        }

        #pragma unroll
        for (int i = 0; i < 18; i++) pv[i] = p[i];
        prow = row;
    }

    // ---- flush last row ----
    {
        #pragma unroll
        for (int i = 0; i < 18; i++) pv[i] += __shfl_xor_sync(FULL, pv[i], 16);
        #pragma unroll
        for (int i = 0; i < 18; i++) pv[i] += __shfl_xor_sync(FULL, pv[i], 8);
        if (lane < 8){
            float* dst = spart[pbuf][warp*8 + lane];
            *(float4*)(dst)      = make_float4(pv[0],  pv[1],  pv[2],  pv[3]);
            *(float4*)(dst + 4)  = make_float4(pv[4],  pv[5],  pv[6],  pv[7]);
            *(float4*)(dst + 8)  = make_float4(pv[8],  pv[9],  pv[10], pv[11]);
            *(float4*)(dst + 12) = make_float4(pv[12], pv[13], pv[14], pv[15]);
            *(float2*)(dst + 16) = make_float2(pv[16], pv[17]);
        }
        __syncthreads();
        if (warp == 0){
            float t0 = 0.f, t1 = 0.f, t2 = 0.f, t3 = 0.f;
            #pragma unroll
            for (int j = 0; j < 64; j += 4){
                t0 += spart[pbuf][j    ][lane];
                t1 += spart[pbuf][j + 1][lane];
                t2 += spart[pbuf][j + 2][lane];
                t3 += spart[pbuf][j + 3][lane];
            }
            float t = (t0 + t1) + (t2 + t3);
            float s1 = __shfl_sync(FULL, t, 16);
            float s2 = __shfl_sync(FULL, t, 17);
            float mu  = s1 * (1.0f/DM);
            float var = s2 * (1.0f/DM) - mu*mu;
            float rs  = rsqrtf(var + 1e-5f);
            if (lane < 16){
                g_u[prow*DS + lane] = fmaf(-mu, cBl, t) * rs + bBl;
            } else if (lane == 16){
                g_murs[prow] = make_float2(mu, rs);
            }
        }
    }
}

// ---------------------------------------------------------------------------
// kernScan: chunked-parallel exact scan (unchanged).
// ---------------------------------------------------------------------------
__global__ __launch_bounds__(32, 1)
void kernScan(const float* __restrict__ A){
    const int chunk = blockIdx.x;
    const int b     = chunk / NCHUNK;
    const int c     = chunk % NCHUNK;
    const int t0    = c * CHL;
    const int start = (c == 0) ? 0 : (t0 - CHW);
    const int steps = t0 + CHL - start;
    const int lane  = threadIdx.x;

    float a[16];
    #pragma unroll
    for (int j = 0; j < 16; j++) a[j] = A[j*DS + (lane & 15)];

    const float* ub = g_u     + (size_t)b * SEQ * DS + (size_t)start * DS;
    float*       hb = g_hist2 + (size_t)(b * SEQ + start) * 32;

    __shared__ float sh[2][32];
    sh[0][lane] = 0.f;
    __syncthreads();

    float uq[4];
    #pragma unroll
    for (int k = 0; k < 4; k++) uq[k] = ub[k*DS + lane];

    const int body0 = t0 - start;
    for (int s = 0; s < steps; s += 4){
        #pragma unroll
        for (int k = 0; k < 4; k++){
            const int i = s + k;
            const int p = i & 1;
            float uc = uq[k];
            uq[k] = ub[(i + 4)*DS + lane];

            float4 H0 = *(const float4*)&sh[p][0];
            float4 H1 = *(const float4*)&sh[p][4];
            float4 H2 = *(const float4*)&sh[p][8];
            float4 H3 = *(const float4*)&sh[p][12];

            float a0 = fmaf(H0.x, a[0], uc);
            float a1 = H0.y * a[1];
            float a2 = H0.z * a[2];
            float a3 = H0.w * a[3];
            float a4 = H1.x * a[4];
            float a5 = H1.y * a[5];
            float a6 = H1.z * a[6];
            float a7 = H1.w * a[7];
            a0 = fmaf(H2.x, a[8],  a0);
            a1 = fmaf(H2.y, a[9],  a1);
            a2 = fmaf(H2.z, a[10], a2);
            a3 = fmaf(H2.w, a[11], a3);
            a4 = fmaf(H3.x, a[12], a4);
            a5 = fmaf(H3.y, a[13], a5);
            a6 = fmaf(H3.z, a[14], a6);
            a7 = fmaf(H3.w, a[15], a7);
            float v = ((a0 + a1) + (a2 + a3)) + ((a4 + a5) + (a6 + a7));
            float h = tanh_fast(v);

            sh[p ^ 1][lane] = h;
            __syncthreads();

            if (i >= body0) hb[i*32 + lane] = h;
        }
    }
}

// ---------------------------------------------------------------------------
// kernC: R14 shape (measured ~52us): R8 scalar core + streaming cache hints
//   (__ldcs x, __stcs out) keeping L2 for C/hist/murs.
// ---------------------------------------------------------------------------
__global__ __launch_bounds__(256, 2)
void kernC(const float* __restrict__ x,
           const float* __restrict__ Cm,
           const float* __restrict__ Dp,
           const float* __restrict__ gamma,
           const float* __restrict__ beta,
           float* __restrict__ out){
    const int tid  = threadIdx.x;
    const int half = blockIdx.x & 1;
    const int d0   = half * (DM/2) + tid * 4;

    float e[4], f[4];
    {
        float4 dp = *(const float4*)(Dp    + d0);
        float4 g  = *(const float4*)(gamma + d0);
        float4 btv= *(const float4*)(beta  + d0);
        float dv[4] = {dp.x,dp.y,dp.z,dp.w};
        float gv[4] = {g.x,g.y,g.z,g.w};
        float bv[4] = {btv.x,btv.y,btv.z,btv.w};
        #pragma unroll
        for (int k = 0; k < 4; k++){
            float cc = 1.0f + dv[k];
            e[k] = cc * gv[k];
            f[k] = cc * bv[k];
        }
    }
    float cr[16][4];
    #pragma unroll
    for (int s = 0; s < 16; s++){
        float4 c0 = *(const float4*)(Cm + s*DM + d0);
        cr[s][0]=c0.x; cr[s][1]=c0.y; cr[s][2]=c0.z; cr[s][3]=c0.w;
    }

    const int base = blockIdx.x >> 1;             // 0..147
    auto ldx = [&](int r){                        // clamp-indexed (branchless)
        int rc = r < NROWS ? r : NROWS-1;
        return __ldcs((const float4*)(x + (size_t)rc*DM + d0));
    };
    float4 x0 = ldx(base);
    float4 x1 = ldx(base + 148);
    float4 p0 = ldx(base + 296);
    float4 p1 = ldx(base + 444);

    for (int r = base; r < NROWS; r += 296){
        float4 c0 = x0, c1 = x1;
        x0 = p0; x1 = p1;
        p0 = ldx(r + 592);
        p1 = ldx(r + 740);

        int rB  = r + 148;
        int rBc = rB < NROWS ? rB : NROWS-1;

        float2 mrA = g_murs[r];
        float2 mrB = g_murs[rBc];
        const float4* hpA = (const float4*)(g_hist2 + (size_t)r*32);
        const float4* hpB = (const float4*)(g_hist2 + (size_t)rBc*32);
        float4 hA0 = hpA[0], hA1 = hpA[1], hA2 = hpA[2], hA3 = hpA[3];
        float4 hB0 = hpB[0], hB1 = hpB[1], hB2 = hpB[2], hB3 = hpB[3];
        float hvA[16] = {hA0.x,hA0.y,hA0.z,hA0.w, hA1.x,hA1.y,hA1.z,hA1.w,
                         hA2.x,hA2.y,hA2.z,hA2.w, hA3.x,hA3.y,hA3.z,hA3.w};
        float hvB[16] = {hB0.x,hB0.y,hB0.z,hB0.w, hB1.x,hB1.y,hB1.z,hB1.w,
                         hB2.x,hB2.y,hB2.z,hB2.w, hB3.x,hB3.y,hB3.z,hB3.w};

        float xsA[4] = {c0.x, c0.y, c0.z, c0.w};
        float xsB[4] = {c1.x, c1.y, c1.z, c1.w};
        float oA[4], oB[4];
        #pragma unroll
        for (int k = 0; k < 4; k++){
            float xcA = (xsA[k] - mrA.x) * mrA.y;
            float xcB = (xsB[k] - mrB.x) * mrB.y;
            float aA  = fmaf(e[k], xcA, f[k]);
            float aB  = fmaf(e[k], xcB, f[k]);
            #pragma unroll
            for (int s = 0; s < 16; s++){
                aA = fmaf(hvA[s], cr[s][k], aA);
                aB = fmaf(hvB[s], cr[s][k], aB);
            }
            oA[k] = aA; oB[k] = aB;
        }
        __stcs((float4*)(out + (size_t)r*DM + d0),
               make_float4(oA[0], oA[1], oA[2], oA[3]));
        if (rB < NROWS)
            __stcs((float4*)(out + (size_t)rB*DM + d0),
                   make_float4(oB[0], oB[1], oB[2], oB[3]));
    }
}

// ---------------------------------------------------------------------------
extern "C" void kernel_launch(void* const* d_in, const int* in_sizes, int n_in,
                              void* d_out, int out_size){
    const float* x     = (const float*)d_in[0];
    const float* A     = (const float*)d_in[1];
    const float* B     = (const float*)d_in[2];
    const float* C     = (const float*)d_in[3];
    const float* Dp    = (const float*)d_in[4];
    const float* gamma = (const float*)d_in[5];
    const float* beta  = (const float*)d_in[6];
    float* out = (float*)d_out;

    kernA<<<148, 256>>>(x, B, gamma, beta);
    kernScan<<<NB*NCHUNK, 32>>>(A);
    kernC<<<296, 256>>>(x, C, Dp, gamma, beta, out);
}

// round 16
// speedup vs baseline: 1.4595x; 1.1306x over previous
#include <cuda_runtime.h>
#include <cstdint>

#define DM 2048
#define DS 16
#define SEQ 4096
#define NB 4
#define NROWS (NB*SEQ)
#define CHL 32                 // scan chunk body length
#define CHW 20                 // scan warmup steps
#define NCHUNK (SEQ/CHL)

typedef unsigned long long u64;

// ---- scratch (static device arrays: no allocation allowed) ----
__device__ float  g_u[NROWS*DS + 1024];
__device__ float2 g_murs[NROWS];
__device__ float  g_hist2[NROWS*32];

__device__ __forceinline__ float tanh_fast(float x){
    float y;
    asm("tanh.approx.f32 %0, %1;" : "=f"(y) : "f"(x));
    return y;
}
__device__ __forceinline__ u64 pk(float lo, float hi){
    u64 d; asm("mov.b64 %0, {%1, %2};" : "=l"(d) : "f"(lo), "f"(hi)); return d;
}
__device__ __forceinline__ float2 unpk(u64 a){
    float2 f; asm("mov.b64 {%0, %1}, %2;" : "=f"(f.x), "=f"(f.y) : "l"(a)); return f;
}
__device__ __forceinline__ u64 fma2(u64 a, u64 b, u64 c){
    u64 d; asm("fma.rn.f32x2 %0, %1, %2, %3;" : "=l"(d) : "l"(a), "l"(b), "l"(c)); return d;
}
__device__ __forceinline__ u64 add2(u64 a, u64 b){
    u64 d; asm("add.rn.f32x2 %0, %1, %2;" : "=l"(d) : "l"(a), "l"(b)); return d;
}
__device__ __forceinline__ void mma_tf32(float* d,
    uint32_t a0, uint32_t a1, uint32_t a2, uint32_t a3,
    uint32_t b0, uint32_t b1){
    asm volatile(
        "mma.sync.aligned.m16n8k8.row.col.f32.tf32.tf32.f32 "
        "{%0,%1,%2,%3}, {%4,%5,%6,%7}, {%8,%9}, {%0,%1,%2,%3};"
        : "+f"(d[0]), "+f"(d[1]), "+f"(d[2]), "+f"(d[3])
        : "r"(a0), "r"(a1), "r"(a2), "r"(a3), "r"(b0), "r"(b1));
}

// smem layout constants (floats)
#define BSTRIDE 2052           // 2048 + 4 pad: bank-conflict-free B frags
#define XSTRIDE 68             // 64 + 4 pad: bank-conflict-free A frags
#define XBUF (128*XSTRIDE)

// ---------------------------------------------------------------------------
// kernA_mma: U = X @ Bg^T via tf32 m16n8k8 tensor cores.
//   128 blocks x 128-row tiles; Bg persistent in smem; x double-buffered in
//   64-wide K chunks. Each warp owns a 16-row tile: D fragments accumulate
//   the full K reduction (no cross-thread reduction, no per-row barrier).
//   LN stats accumulate in packed registers during staging.
// ---------------------------------------------------------------------------
__global__ __launch_bounds__(256, 1)
void kernA_mma(const float* __restrict__ x,
               const float* __restrict__ B,
               const float* __restrict__ gamma,
               const float* __restrict__ beta){
    extern __shared__ float sm[];
    float*  Bsm   = sm;                          // 16*2052
    float*  Xsm   = Bsm + 16*BSTRIDE;            // 2*128*68
    float2* murs2 = (float2*)(Xsm + 2*XBUF);     // 128
    float*  red   = (float*)(murs2 + 128);       // 256
    float*  scb   = red + 256;                   // 32

    const int tid  = threadIdx.x;
    const int lane = tid & 31, warp = tid >> 5;
    const unsigned FULL = 0xFFFFFFFFu;
    const int R = blockIdx.x * 128;

    // ---- prologue: gamma-fold B into Bsm, compute cB/bB ----
    {
        const int d0 = tid * 8;
        float4 g0 = *(const float4*)(gamma + d0);
        float4 g1 = *(const float4*)(gamma + d0 + 4);
        float4 e0 = *(const float4*)(beta  + d0);
        float4 e1 = *(const float4*)(beta  + d0 + 4);
        float gg[8] = {g0.x,g0.y,g0.z,g0.w,g1.x,g1.y,g1.z,g1.w};
        float bt[8] = {e0.x,e0.y,e0.z,e0.w,e1.x,e1.y,e1.z,e1.w};
        float pc[16], pb[16];
        #pragma unroll
        for (int s = 0; s < 16; s++){
            float4 b0 = *(const float4*)(B + s*DM + d0);
            float4 b1 = *(const float4*)(B + s*DM + d0 + 4);
            float br[8] = {b0.x,b0.y,b0.z,b0.w,b1.x,b1.y,b1.z,b1.w};
            float fd[8];
            float c = 0.f, b2 = 0.f;
            #pragma unroll
            for (int k = 0; k < 8; k++){
                fd[k] = br[k] * gg[k];
                c += fd[k];
                b2 = fmaf(bt[k], br[k], b2);
            }
            *(float4*)(Bsm + s*BSTRIDE + d0)     = make_float4(fd[0],fd[1],fd[2],fd[3]);
            *(float4*)(Bsm + s*BSTRIDE + d0 + 4) = make_float4(fd[4],fd[5],fd[6],fd[7]);
            pc[s] = c; pb[s] = b2;
        }
        #pragma unroll
        for (int off = 16; off > 0; off >>= 1){
            #pragma unroll
            for (int s = 0; s < 16; s++){
                pc[s] += __shfl_xor_sync(FULL, pc[s], off);
                pb[s] += __shfl_xor_sync(FULL, pb[s], off);
            }
        }
        if (lane == 0){
            #pragma unroll
            for (int s = 0; s < 16; s++){
                red[warp*32 + s]      = pc[s];
                red[warp*32 + 16 + s] = pb[s];
            }
        }
        __syncthreads();
        if (tid < 32){
            float t = red[tid];
            #pragma unroll
            for (int w = 1; w < 8; w++) t += red[w*32 + tid];
            scb[tid] = t;
        }
        __syncthreads();
    }

    const int g = lane >> 2, q = lane & 3;
    float cBe[4], bBe[4];
    {
        int sl[4] = {2*q, 2*q+1, 8+2*q, 9+2*q};
        #pragma unroll
        for (int j = 0; j < 4; j++){ cBe[j] = scb[sl[j]]; bBe[j] = scb[16 + sl[j]]; }
    }

    // ---- main loop: 32 K-chunks of 64 ----
    const int rs0 = tid >> 4;     // row-set (0..15)
    const int cg  = tid & 15;     // col group
    u64 asum[8], assq[8];
    #pragma unroll
    for (int i = 0; i < 8; i++){ asum[i] = pk(0.f,0.f); assq[i] = pk(0.f,0.f); }
    float acc0[4] = {0.f,0.f,0.f,0.f};
    float acc1[4] = {0.f,0.f,0.f,0.f};

    for (int c = 0; c < 32; c++){
        float* Xb = Xsm + (c & 1) * XBUF;
        const int k0 = c * 64;
        // stage 128 rows x 64 cols (+ stats)
        #pragma unroll
        for (int i = 0; i < 8; i++){
            int row = rs0 + 16*i;
            float4 v = __ldcs((const float4*)(x + (size_t)(R+row)*DM + k0 + cg*4));
            u64 p1 = pk(v.x, v.y), p2 = pk(v.z, v.w);
            asum[i] = add2(add2(asum[i], p1), p2);
            assq[i] = fma2(p1, p1, assq[i]);
            assq[i] = fma2(p2, p2, assq[i]);
            *(float4*)(Xb + row*XSTRIDE + cg*4) = v;
        }
        __syncthreads();
        // mma: 8 ksteps of k8
        const float* Ar1 = Xb + (warp*16 + g)*XSTRIDE;
        const float* Ar2 = Ar1 + 8*XSTRIDE;
        const float* Bn0 = Bsm + g*BSTRIDE + k0;
        const float* Bn1 = Bsm + (8+g)*BSTRIDE + k0;
        #pragma unroll
        for (int kk = 0; kk < 8; kk++){
            int kq = kk*8 + q;
            uint32_t a0 = __float_as_uint(Ar1[kq]);
            uint32_t a1 = __float_as_uint(Ar2[kq]);
            uint32_t a2 = __float_as_uint(Ar1[kq+4]);
            uint32_t a3 = __float_as_uint(Ar2[kq+4]);
            uint32_t b0 = __float_as_uint(Bn0[kq]);
            uint32_t b1 = __float_as_uint(Bn0[kq+4]);
            mma_tf32(acc0, a0,a1,a2,a3, b0,b1);
            uint32_t b2 = __float_as_uint(Bn1[kq]);
            uint32_t b3 = __float_as_uint(Bn1[kq+4]);
            mma_tf32(acc1, a0,a1,a2,a3, b2,b3);
        }
        // safety: each thread's mma(c) precedes its stage(c+1); the sync in
        // chunk c+1 orders all warps' stage(c+1) (hence their mma(c)) before
        // any stage(c+2) rewrite of this buffer.
    }

    // ---- stats epilogue: 16-lane butterfly per row-set ----
    {
        float fsum[8], fssq[8];
        #pragma unroll
        for (int i = 0; i < 8; i++){
            float2 a = unpk(asum[i]); fsum[i] = a.x + a.y;
            float2 b = unpk(assq[i]); fssq[i] = b.x + b.y;
        }
        #pragma unroll
        for (int off = 1; off < 16; off <<= 1){
            #pragma unroll
            for (int i = 0; i < 8; i++){
                fsum[i] += __shfl_xor_sync(FULL, fsum[i], off);
                fssq[i] += __shfl_xor_sync(FULL, fssq[i], off);
            }
        }
        if (cg == 0){
            #pragma unroll
            for (int i = 0; i < 8; i++){
                int row = rs0 + 16*i;
                float mu  = fsum[i] * (1.0f/DM);
                float var = fssq[i] * (1.0f/DM) - mu*mu;
                float rs  = rsqrtf(var + 1e-5f);
                float2 mr = make_float2(mu, rs);
                murs2[row] = mr;
                g_murs[R + row] = mr;
            }
        }
    }
    __syncthreads();

    // ---- u epilogue: lane owns rows (16w+g, +8), cols {2q,2q+1,8+2q,9+2q} ----
    {
        int r1 = warp*16 + g, r2 = r1 + 8;
        float2 m1 = murs2[r1], m2 = murs2[r2];
        float u00 = fmaf(-m1.x, cBe[0], acc0[0]) * m1.y + bBe[0];
        float u01 = fmaf(-m1.x, cBe[1], acc0[1]) * m1.y + bBe[1];
        float u10 = fmaf(-m2.x, cBe[0], acc0[2]) * m2.y + bBe[0];
        float u11 = fmaf(-m2.x, cBe[1], acc0[3]) * m2.y + bBe[1];
        float u02 = fmaf(-m1.x, cBe[2], acc1[0]) * m1.y + bBe[2];
        float u03 = fmaf(-m1.x, cBe[3], acc1[1]) * m1.y + bBe[3];
        float u12 = fmaf(-m2.x, cBe[2], acc1[2]) * m2.y + bBe[2];
        float u13 = fmaf(-m2.x, cBe[3], acc1[3]) * m2.y + bBe[3];
        float* up1 = g_u + (size_t)(R + r1)*DS;
        float* up2 = g_u + (size_t)(R + r2)*DS;
        *(float2*)(up1 + 2*q)     = make_float2(u00, u01);
        *(float2*)(up1 + 8 + 2*q) = make_float2(u02, u03);
        *(float2*)(up2 + 2*q)     = make_float2(u10, u11);
        *(float2*)(up2 + 8 + 2*q) = make_float2(u12, u13);
    }
}

// ---------------------------------------------------------------------------
// kernScan: chunked-parallel exact scan (unchanged, measured best).
// ---------------------------------------------------------------------------
__global__ __launch_bounds__(32, 1)
void kernScan(const float* __restrict__ A){
    const int chunk = blockIdx.x;
    const int b     = chunk / NCHUNK;
    const int c     = chunk % NCHUNK;
    const int t0    = c * CHL;
    const int start = (c == 0) ? 0 : (t0 - CHW);
    const int steps = t0 + CHL - start;
    const int lane  = threadIdx.x;

    float a[16];
    #pragma unroll
    for (int j = 0; j < 16; j++) a[j] = A[j*DS + (lane & 15)];

    const float* ub = g_u     + (size_t)b * SEQ * DS + (size_t)start * DS;
    float*       hb = g_hist2 + (size_t)(b * SEQ + start) * 32;

    __shared__ float sh[2][32];
    sh[0][lane] = 0.f;
    __syncthreads();

    float uq[4];
    #pragma unroll
    for (int k = 0; k < 4; k++) uq[k] = ub[k*DS + lane];

    const int body0 = t0 - start;
    for (int s = 0; s < steps; s += 4){
        #pragma unroll
        for (int k = 0; k < 4; k++){
            const int i = s + k;
            const int p = i & 1;
            float uc = uq[k];
            uq[k] = ub[(i + 4)*DS + lane];

            float4 H0 = *(const float4*)&sh[p][0];
            float4 H1 = *(const float4*)&sh[p][4];
            float4 H2 = *(const float4*)&sh[p][8];
            float4 H3 = *(const float4*)&sh[p][12];

            float a0 = fmaf(H0.x, a[0], uc);
            float a1 = H0.y * a[1];
            float a2 = H0.z * a[2];
            float a3 = H0.w * a[3];
            float a4 = H1.x * a[4];
            float a5 = H1.y * a[5];
            float a6 = H1.z * a[6];
            float a7 = H1.w * a[7];
            a0 = fmaf(H2.x, a[8],  a0);
            a1 = fmaf(H2.y, a[9],  a1);
            a2 = fmaf(H2.z, a[10], a2);
            a3 = fmaf(H2.w, a[11], a3);
            a4 = fmaf(H3.x, a[12], a4);
            a5 = fmaf(H3.y, a[13], a5);
            a6 = fmaf(H3.z, a[14], a6);
            a7 = fmaf(H3.w, a[15], a7);
            float v = ((a0 + a1) + (a2 + a3)) + ((a4 + a5) + (a6 + a7));
            float h = tanh_fast(v);

            sh[p ^ 1][lane] = h;
            __syncthreads();

            if (i >= body0) hb[i*32 + lane] = h;
        }
    }
}

// ---------------------------------------------------------------------------
// kernC: R14/R15 shape (measured ~52us): scalar core + streaming hints.
// ---------------------------------------------------------------------------
__global__ __launch_bounds__(256, 2)
void kernC(const float* __restrict__ x,
           const float* __restrict__ Cm,
           const float* __restrict__ Dp,
           const float* __restrict__ gamma,
           const float* __restrict__ beta,
           float* __restrict__ out){
    const int tid  = threadIdx.x;
    const int half = blockIdx.x & 1;
    const int d0   = half * (DM/2) + tid * 4;

    float e[4], f[4];
    {
        float4 dp = *(const float4*)(Dp    + d0);
        float4 g  = *(const float4*)(gamma + d0);
        float4 btv= *(const float4*)(beta  + d0);
        float dv[4] = {dp.x,dp.y,dp.z,dp.w};
        float gv[4] = {g.x,g.y,g.z,g.w};
        float bv[4] = {btv.x,btv.y,btv.z,btv.w};
        #pragma unroll
        for (int k = 0; k < 4; k++){
            float cc = 1.0f + dv[k];
            e[k] = cc * gv[k];
            f[k] = cc * bv[k];
        }
    }
    float cr[16][4];
    #pragma unroll
    for (int s = 0; s < 16; s++){
        float4 c0 = *(const float4*)(Cm + s*DM + d0);
        cr[s][0]=c0.x; cr[s][1]=c0.y; cr[s][2]=c0.z; cr[s][3]=c0.w;
    }

    const int base = blockIdx.x >> 1;
    auto ldx = [&](int r){
        int rc = r < NROWS ? r : NROWS-1;
        return __ldcs((const float4*)(x + (size_t)rc*DM + d0));
    };
    float4 x0 = ldx(base);
    float4 x1 = ldx(base + 148);
    float4 p0 = ldx(base + 296);
    float4 p1 = ldx(base + 444);

    for (int r = base; r < NROWS; r += 296){
        float4 c0 = x0, c1 = x1;
        x0 = p0; x1 = p1;
        p0 = ldx(r + 592);
        p1 = ldx(r + 740);

        int rB  = r + 148;
        int rBc = rB < NROWS ? rB : NROWS-1;

        float2 mrA = g_murs[r];
        float2 mrB = g_murs[rBc];
        const float4* hpA = (const float4*)(g_hist2 + (size_t)r*32);
        const float4* hpB = (const float4*)(g_hist2 + (size_t)rBc*32);
        float4 hA0 = hpA[0], hA1 = hpA[1], hA2 = hpA[2], hA3 = hpA[3];
        float4 hB0 = hpB[0], hB1 = hpB[1], hB2 = hpB[2], hB3 = hpB[3];
        float hvA[16] = {hA0.x,hA0.y,hA0.z,hA0.w, hA1.x,hA1.y,hA1.z,hA1.w,
                         hA2.x,hA2.y,hA2.z,hA2.w, hA3.x,hA3.y,hA3.z,hA3.w};
        float hvB[16] = {hB0.x,hB0.y,hB0.z,hB0.w, hB1.x,hB1.y,hB1.z,hB1.w,
                         hB2.x,hB2.y,hB2.z,hB2.w, hB3.x,hB3.y,hB3.z,hB3.w};

        float xsA[4] = {c0.x, c0.y, c0.z, c0.w};
        float xsB[4] = {c1.x, c1.y, c1.z, c1.w};
        float oA[4], oB[4];
        #pragma unroll
        for (int k = 0; k < 4; k++){
            float xcA = (xsA[k] - mrA.x) * mrA.y;
            float xcB = (xsB[k] - mrB.x) * mrB.y;
            float aA  = fmaf(e[k], xcA, f[k]);
            float aB  = fmaf(e[k], xcB, f[k]);
            #pragma unroll
            for (int s = 0; s < 16; s++){
                aA = fmaf(hvA[s], cr[s][k], aA);
                aB = fmaf(hvB[s], cr[s][k], aB);
            }
            oA[k] = aA; oB[k] = aB;
        }
        __stcs((float4*)(out + (size_t)r*DM + d0),
               make_float4(oA[0], oA[1], oA[2], oA[3]));
        if (rB < NROWS)
            __stcs((float4*)(out + (size_t)rB*DM + d0),
                   make_float4(oB[0], oB[1], oB[2], oB[3]));
    }
}

// ---------------------------------------------------------------------------
extern "C" void kernel_launch(void* const* d_in, const int* in_sizes, int n_in,
                              void* d_out, int out_size){
    const float* x     = (const float*)d_in[0];
    const float* A     = (const float*)d_in[1];
    const float* B     = (const float*)d_in[2];
    const float* C     = (const float*)d_in[3];
    const float* Dp    = (const float*)d_in[4];
    const float* gamma = (const float*)d_in[5];
    const float* beta  = (const float*)d_in[6];
    float* out = (float*)d_out;

    const int smemA = (16*BSTRIDE + 2*XBUF + 256 + 256 + 32) * 4;  // ~203 KB
    cudaFuncSetAttribute(kernA_mma, cudaFuncAttributeMaxDynamicSharedMemorySize, smemA);
    kernA_mma<<<128, 256, smemA>>>(x, B, gamma, beta);
    kernScan<<<NB*NCHUNK, 32>>>(A);
    kernC<<<296, 256>>>(x, C, Dp, gamma, beta, out);
}

// round 17
// speedup vs baseline: 1.5399x; 1.0551x over previous
#include <cuda_runtime.h>
#include <cstdint>

#define DM 2048
#define DS 16
#define SEQ 4096
#define NB 4
#define NROWS (NB*SEQ)
#define CHL 32                 // scan chunk body length
#define CHW 20                 // scan warmup steps
#define NCHUNK (SEQ/CHL)

typedef unsigned long long u64;

// ---- scratch (static device arrays: no allocation allowed) ----
__device__ float  g_u[NROWS*DS + 1024];
__device__ float2 g_murs[NROWS];
__device__ float  g_hist2[NROWS*32];

__device__ __forceinline__ float tanh_fast(float x){
    float y;
    asm("tanh.approx.f32 %0, %1;" : "=f"(y) : "f"(x));
    return y;
}
__device__ __forceinline__ u64 pk(float lo, float hi){
    u64 d; asm("mov.b64 %0, {%1, %2};" : "=l"(d) : "f"(lo), "f"(hi)); return d;
}
__device__ __forceinline__ float2 unpk(u64 a){
    float2 f; asm("mov.b64 {%0, %1}, %2;" : "=f"(f.x), "=f"(f.y) : "l"(a)); return f;
}
__device__ __forceinline__ u64 fma2(u64 a, u64 b, u64 c){
    u64 d; asm("fma.rn.f32x2 %0, %1, %2, %3;" : "=l"(d) : "l"(a), "l"(b), "l"(c)); return d;
}
__device__ __forceinline__ u64 add2(u64 a, u64 b){
    u64 d; asm("add.rn.f32x2 %0, %1, %2;" : "=l"(d) : "l"(a), "l"(b)); return d;
}
__device__ __forceinline__ void mma_tf32(float* d,
    uint32_t a0, uint32_t a1, uint32_t a2, uint32_t a3,
    uint32_t b0, uint32_t b1){
    asm volatile(
        "mma.sync.aligned.m16n8k8.row.col.f32.tf32.tf32.f32 "
        "{%0,%1,%2,%3}, {%4,%5,%6,%7}, {%8,%9}, {%0,%1,%2,%3};"
        : "+f"(d[0]), "+f"(d[1]), "+f"(d[2]), "+f"(d[3])
        : "r"(a0), "r"(a1), "r"(a2), "r"(a3), "r"(b0), "r"(b1));
}

// smem layout constants (floats)
#define BSTRIDE 2052           // 2048 + 4 pad: bank-conflict-free B frags
#define XSTRIDE 68             // 64 + 4 pad: bank-conflict-free A frags
#define XBUF (128*XSTRIDE)

// ---------------------------------------------------------------------------
// kernA_mma: U = X @ Bg^T via tf32 m16n8k8 tensor cores.
//   R17: register-staged software pipeline — chunk c+1 held in registers;
//   its successor's loads issue right after the sync, draining under the
//   mma of chunk c. One sync per chunk.
// ---------------------------------------------------------------------------
__global__ __launch_bounds__(256, 1)
void kernA_mma(const float* __restrict__ x,
               const float* __restrict__ B,
               const float* __restrict__ gamma,
               const float* __restrict__ beta){
    extern __shared__ float sm[];
    float*  Bsm   = sm;                          // 16*2052
    float*  Xsm   = Bsm + 16*BSTRIDE;            // 2*128*68
    float2* murs2 = (float2*)(Xsm + 2*XBUF);     // 128
    float*  red   = (float*)(murs2 + 128);       // 256
    float*  scb   = red + 256;                   // 32

    const int tid  = threadIdx.x;
    const int lane = tid & 31, warp = tid >> 5;
    const unsigned FULL = 0xFFFFFFFFu;
    const int R = blockIdx.x * 128;

    // ---- prologue: gamma-fold B into Bsm, compute cB/bB ----
    {
        const int d0 = tid * 8;
        float4 g0 = *(const float4*)(gamma + d0);
        float4 g1 = *(const float4*)(gamma + d0 + 4);
        float4 e0 = *(const float4*)(beta  + d0);
        float4 e1 = *(const float4*)(beta  + d0 + 4);
        float gg[8] = {g0.x,g0.y,g0.z,g0.w,g1.x,g1.y,g1.z,g1.w};
        float bt[8] = {e0.x,e0.y,e0.z,e0.w,e1.x,e1.y,e1.z,e1.w};
        float pc[16], pb[16];
        #pragma unroll
        for (int s = 0; s < 16; s++){
            float4 b0 = *(const float4*)(B + s*DM + d0);
            float4 b1 = *(const float4*)(B + s*DM + d0 + 4);
            float br[8] = {b0.x,b0.y,b0.z,b0.w,b1.x,b1.y,b1.z,b1.w};
            float fd[8];
            float c = 0.f, b2 = 0.f;
            #pragma unroll
            for (int k = 0; k < 8; k++){
                fd[k] = br[k] * gg[k];
                c += fd[k];
                b2 = fmaf(bt[k], br[k], b2);
            }
            *(float4*)(Bsm + s*BSTRIDE + d0)     = make_float4(fd[0],fd[1],fd[2],fd[3]);
            *(float4*)(Bsm + s*BSTRIDE + d0 + 4) = make_float4(fd[4],fd[5],fd[6],fd[7]);
            pc[s] = c; pb[s] = b2;
        }
        #pragma unroll
        for (int off = 16; off > 0; off >>= 1){
            #pragma unroll
            for (int s = 0; s < 16; s++){
                pc[s] += __shfl_xor_sync(FULL, pc[s], off);
                pb[s] += __shfl_xor_sync(FULL, pb[s], off);
            }
        }
        if (lane == 0){
            #pragma unroll
            for (int s = 0; s < 16; s++){
                red[warp*32 + s]      = pc[s];
                red[warp*32 + 16 + s] = pb[s];
            }
        }
        __syncthreads();
        if (tid < 32){
            float t = red[tid];
            #pragma unroll
            for (int w = 1; w < 8; w++) t += red[w*32 + tid];
            scb[tid] = t;
        }
        __syncthreads();
    }

    const int g = lane >> 2, q = lane & 3;
    float cBe[4], bBe[4];
    {
        int sl[4] = {2*q, 2*q+1, 8+2*q, 9+2*q};
        #pragma unroll
        for (int j = 0; j < 4; j++){ cBe[j] = scb[sl[j]]; bBe[j] = scb[16 + sl[j]]; }
    }

    // ---- main loop: 32 K-chunks of 64, register-staged pipeline ----
    const int rs0 = tid >> 4;     // row-set (0..15)
    const int cg  = tid & 15;     // col group
    u64 asum[8], assq[8];
    #pragma unroll
    for (int i = 0; i < 8; i++){ asum[i] = pk(0.f,0.f); assq[i] = pk(0.f,0.f); }
    float acc0[4] = {0.f,0.f,0.f,0.f};
    float acc1[4] = {0.f,0.f,0.f,0.f};

    float4 v[8];                  // in-flight chunk (registers)
    #pragma unroll
    for (int i = 0; i < 8; i++){
        int row = rs0 + 16*i;
        v[i] = __ldcs((const float4*)(x + (size_t)(R+row)*DM + cg*4));
    }

    for (int c = 0; c < 32; c++){
        float* Xb = Xsm + (c & 1) * XBUF;
        const int k0 = c * 64;
        // commit registers -> smem (+ stats)
        #pragma unroll
        for (int i = 0; i < 8; i++){
            int row = rs0 + 16*i;
            u64 p1 = pk(v[i].x, v[i].y), p2 = pk(v[i].z, v[i].w);
            asum[i] = add2(add2(asum[i], p1), p2);
            assq[i] = fma2(p1, p1, assq[i]);
            assq[i] = fma2(p2, p2, assq[i]);
            *(float4*)(Xb + row*XSTRIDE + cg*4) = v[i];
        }
        __syncthreads();
        // issue next chunk's loads NOW — they drain under the mma below
        if (c < 31){
            const int kn = k0 + 64;
            #pragma unroll
            for (int i = 0; i < 8; i++){
                int row = rs0 + 16*i;
                v[i] = __ldcs((const float4*)(x + (size_t)(R+row)*DM + kn + cg*4));
            }
        }
        // mma: 8 ksteps of k8 on chunk c
        const float* Ar1 = Xb + (warp*16 + g)*XSTRIDE;
        const float* Ar2 = Ar1 + 8*XSTRIDE;
        const float* Bn0 = Bsm + g*BSTRIDE + k0;
        const float* Bn1 = Bsm + (8+g)*BSTRIDE + k0;
        #pragma unroll
        for (int kk = 0; kk < 8; kk++){
            int kq = kk*8 + q;
            uint32_t a0 = __float_as_uint(Ar1[kq]);
            uint32_t a1 = __float_as_uint(Ar2[kq]);
            uint32_t a2 = __float_as_uint(Ar1[kq+4]);
            uint32_t a3 = __float_as_uint(Ar2[kq+4]);
            uint32_t b0 = __float_as_uint(Bn0[kq]);
            uint32_t b1 = __float_as_uint(Bn0[kq+4]);
            mma_tf32(acc0, a0,a1,a2,a3, b0,b1);
            uint32_t b2 = __float_as_uint(Bn1[kq]);
            uint32_t b3 = __float_as_uint(Bn1[kq+4]);
            mma_tf32(acc1, a0,a1,a2,a3, b2,b3);
        }
        // buffer safety: mma(c-1) precedes store(c) in program order; the
        // sync in chunk c fences all warps' mma(c-1) before store(c+1).
    }

    // ---- stats epilogue: 16-lane butterfly per row-set ----
    {
        float fsum[8], fssq[8];
        #pragma unroll
        for (int i = 0; i < 8; i++){
            float2 a = unpk(asum[i]); fsum[i] = a.x + a.y;
            float2 b = unpk(assq[i]); fssq[i] = b.x + b.y;
        }
        #pragma unroll
        for (int off = 1; off < 16; off <<= 1){
            #pragma unroll
            for (int i = 0; i < 8; i++){
                fsum[i] += __shfl_xor_sync(FULL, fsum[i], off);
                fssq[i] += __shfl_xor_sync(FULL, fssq[i], off);
            }
        }
        if (cg == 0){
            #pragma unroll
            for (int i = 0; i < 8; i++){
                int row = rs0 + 16*i;
                float mu  = fsum[i] * (1.0f/DM);
                float var = fssq[i] * (1.0f/DM) - mu*mu;
                float rs  = rsqrtf(var + 1e-5f);
                float2 mr = make_float2(mu, rs);
                murs2[row] = mr;
                g_murs[R + row] = mr;
            }
        }
    }
    __syncthreads();

    // ---- u epilogue ----
    {
        int r1 = warp*16 + g, r2 = r1 + 8;
        float2 m1 = murs2[r1], m2 = murs2[r2];
        float u00 = fmaf(-m1.x, cBe[0], acc0[0]) * m1.y + bBe[0];
        float u01 = fmaf(-m1.x, cBe[1], acc0[1]) * m1.y + bBe[1];
        float u10 = fmaf(-m2.x, cBe[0], acc0[2]) * m2.y + bBe[0];
        float u11 = fmaf(-m2.x, cBe[1], acc0[3]) * m2.y + bBe[1];
        float u02 = fmaf(-m1.x, cBe[2], acc1[0]) * m1.y + bBe[2];
        float u03 = fmaf(-m1.x, cBe[3], acc1[1]) * m1.y + bBe[3];
        float u12 = fmaf(-m2.x, cBe[2], acc1[2]) * m2.y + bBe[2];
        float u13 = fmaf(-m2.x, cBe[3], acc1[3]) * m2.y + bBe[3];
        float* up1 = g_u + (size_t)(R + r1)*DS;
        float* up2 = g_u + (size_t)(R + r2)*DS;
        *(float2*)(up1 + 2*q)     = make_float2(u00, u01);
        *(float2*)(up1 + 8 + 2*q) = make_float2(u02, u03);
        *(float2*)(up2 + 2*q)     = make_float2(u10, u11);
        *(float2*)(up2 + 8 + 2*q) = make_float2(u12, u13);
    }
}

// ---------------------------------------------------------------------------
// kernScan: chunked-parallel exact scan (unchanged, measured best).
// ---------------------------------------------------------------------------
__global__ __launch_bounds__(32, 1)
void kernScan(const float* __restrict__ A){
    const int chunk = blockIdx.x;
    const int b     = chunk / NCHUNK;
    const int c     = chunk % NCHUNK;
    const int t0    = c * CHL;
    const int start = (c == 0) ? 0 : (t0 - CHW);
    const int steps = t0 + CHL - start;
    const int lane  = threadIdx.x;

    float a[16];
    #pragma unroll
    for (int j = 0; j < 16; j++) a[j] = A[j*DS + (lane & 15)];

    const float* ub = g_u     + (size_t)b * SEQ * DS + (size_t)start * DS;
    float*       hb = g_hist2 + (size_t)(b * SEQ + start) * 32;

    __shared__ float sh[2][32];
    sh[0][lane] = 0.f;
    __syncthreads();

    float uq[4];
    #pragma unroll
    for (int k = 0; k < 4; k++) uq[k] = ub[k*DS + lane];

    const int body0 = t0 - start;
    for (int s = 0; s < steps; s += 4){
        #pragma unroll
        for (int k = 0; k < 4; k++){
            const int i = s + k;
            const int p = i & 1;
            float uc = uq[k];
            uq[k] = ub[(i + 4)*DS + lane];

            float4 H0 = *(const float4*)&sh[p][0];
            float4 H1 = *(const float4*)&sh[p][4];
            float4 H2 = *(const float4*)&sh[p][8];
            float4 H3 = *(const float4*)&sh[p][12];

            float a0 = fmaf(H0.x, a[0], uc);
            float a1 = H0.y * a[1];
            float a2 = H0.z * a[2];
            float a3 = H0.w * a[3];
            float a4 = H1.x * a[4];
            float a5 = H1.y * a[5];
            float a6 = H1.z * a[6];
            float a7 = H1.w * a[7];
            a0 = fmaf(H2.x, a[8],  a0);
            a1 = fmaf(H2.y, a[9],  a1);
            a2 = fmaf(H2.z, a[10], a2);
            a3 = fmaf(H2.w, a[11], a3);
            a4 = fmaf(H3.x, a[12], a4);
            a5 = fmaf(H3.y, a[13], a5);
            a6 = fmaf(H3.z, a[14], a6);
            a7 = fmaf(H3.w, a[15], a7);
            float v = ((a0 + a1) + (a2 + a3)) + ((a4 + a5) + (a6 + a7));
            float h = tanh_fast(v);

            sh[p ^ 1][lane] = h;
            __syncthreads();

            if (i >= body0) hb[i*32 + lane] = h;
        }
    }
}

// ---------------------------------------------------------------------------
// kernC: R14/R15 shape (measured ~52us): scalar core + streaming hints.
// ---------------------------------------------------------------------------
__global__ __launch_bounds__(256, 2)
void kernC(const float* __restrict__ x,
           const float* __restrict__ Cm,
           const float* __restrict__ Dp,
           const float* __restrict__ gamma,
           const float* __restrict__ beta,
           float* __restrict__ out){
    const int tid  = threadIdx.x;
    const int half = blockIdx.x & 1;
    const int d0   = half * (DM/2) + tid * 4;

    float e[4], f[4];
    {
        float4 dp = *(const float4*)(Dp    + d0);
        float4 g  = *(const float4*)(gamma + d0);
        float4 btv= *(const float4*)(beta  + d0);
        float dv[4] = {dp.x,dp.y,dp.z,dp.w};
        float gv[4] = {g.x,g.y,g.z,g.w};
        float bv[4] = {btv.x,btv.y,btv.z,btv.w};
        #pragma unroll
        for (int k = 0; k < 4; k++){
            float cc = 1.0f + dv[k];
            e[k] = cc * gv[k];
            f[k] = cc * bv[k];
        }
    }
    float cr[16][4];
    #pragma unroll
    for (int s = 0; s < 16; s++){
        float4 c0 = *(const float4*)(Cm + s*DM + d0);
        cr[s][0]=c0.x; cr[s][1]=c0.y; cr[s][2]=c0.z; cr[s][3]=c0.w;
    }

    const int base = blockIdx.x >> 1;
    auto ldx = [&](int r){
        int rc = r < NROWS ? r : NROWS-1;
        return __ldcs((const float4*)(x + (size_t)rc*DM + d0));
    };
    float4 x0 = ldx(base);
    float4 x1 = ldx(base + 148);
    float4 p0 = ldx(base + 296);
    float4 p1 = ldx(base + 444);

    for (int r = base; r < NROWS; r += 296){
        float4 c0 = x0, c1 = x1;
        x0 = p0; x1 = p1;
        p0 = ldx(r + 592);
        p1 = ldx(r + 740);

        int rB  = r + 148;
        int rBc = rB < NROWS ? rB : NROWS-1;

        float2 mrA = g_murs[r];
        float2 mrB = g_murs[rBc];
        const float4* hpA = (const float4*)(g_hist2 + (size_t)r*32);
        const float4* hpB = (const float4*)(g_hist2 + (size_t)rBc*32);
        float4 hA0 = hpA[0], hA1 = hpA[1], hA2 = hpA[2], hA3 = hpA[3];
        float4 hB0 = hpB[0], hB1 = hpB[1], hB2 = hpB[2], hB3 = hpB[3];
        float hvA[16] = {hA0.x,hA0.y,hA0.z,hA0.w, hA1.x,hA1.y,hA1.z,hA1.w,
                         hA2.x,hA2.y,hA2.z,hA2.w, hA3.x,hA3.y,hA3.z,hA3.w};
        float hvB[16] = {hB0.x,hB0.y,hB0.z,hB0.w, hB1.x,hB1.y,hB1.z,hB1.w,
                         hB2.x,hB2.y,hB2.z,hB2.w, hB3.x,hB3.y,hB3.z,hB3.w};

        float xsA[4] = {c0.x, c0.y, c0.z, c0.w};
        float xsB[4] = {c1.x, c1.y, c1.z, c1.w};
        float oA[4], oB[4];
        #pragma unroll
        for (int k = 0; k < 4; k++){
            float xcA = (xsA[k] - mrA.x) * mrA.y;
            float xcB = (xsB[k] - mrB.x) * mrB.y;
            float aA  = fmaf(e[k], xcA, f[k]);
            float aB  = fmaf(e[k], xcB, f[k]);
            #pragma unroll
            for (int s = 0; s < 16; s++){
                aA = fmaf(hvA[s], cr[s][k], aA);
                aB = fmaf(hvB[s], cr[s][k], aB);
            }
            oA[k] = aA; oB[k] = aB;
        }
        __stcs((float4*)(out + (size_t)r*DM + d0),
               make_float4(oA[0], oA[1], oA[2], oA[3]));
        if (rB < NROWS)
            __stcs((float4*)(out + (size_t)rB*DM + d0),
                   make_float4(oB[0], oB[1], oB[2], oB[3]));
    }
}

// ---------------------------------------------------------------------------
extern "C" void kernel_launch(void* const* d_in, const int* in_sizes, int n_in,
                              void* d_out, int out_size){
    const float* x     = (const float*)d_in[0];
    const float* A     = (const float*)d_in[1];
    const float* B     = (const float*)d_in[2];
    const float* C     = (const float*)d_in[3];
    const float* Dp    = (const float*)d_in[4];
    const float* gamma = (const float*)d_in[5];
    const float* beta  = (const float*)d_in[6];
    float* out = (float*)d_out;

    const int smemA = (16*BSTRIDE + 2*XBUF + 256 + 256 + 32) * 4;  // ~203 KB
    cudaFuncSetAttribute(kernA_mma, cudaFuncAttributeMaxDynamicSharedMemorySize, smemA);
    kernA_mma<<<128, 256, smemA>>>(x, B, gamma, beta);
    kernScan<<<NB*NCHUNK, 32>>>(A);
    kernC<<<296, 256>>>(x, C, Dp, gamma, beta, out);
}